// round 2
// baseline (speedup 1.0000x reference)
#include <cuda_runtime.h>
#include <math.h>

// Problem constants
#define AA    64
#define EP    8
#define ETOT  512            // AA*EP
#define HH    768
#define HI    1536
#define DD    100
#define MM    32768          // AA*ETOT
#define SCORES_N 262144      // 1*64*64*8*8
#define OFF_SCORES 0
#define OFF_VGS    262144
#define OFF_IDX    262656

// Scratch: h = LN(GELU(E@W1+b1))  [32768, 1536] fp32 = 192 MiB
__device__ float g_h[(size_t)MM * HI];
__device__ int   g_sel;

// ---------------------------------------------------------------------------
// Kernel 1: C = GELU(A@B + bias), A=[M,K]=E(flat), B=[K,N]=W1
// M=32768, K=768, N=1536. 128x128 tile, BK=8, 256 threads, 8x8/thread,
// double-buffered smem.
// ---------------------------------------------------------------------------
__global__ void __launch_bounds__(256, 2)
gemm1_kernel(const float* __restrict__ A, const float* __restrict__ B,
             const float* __restrict__ bias) {
    const int K = HH, N = HI;
    __shared__ float As[2][8][128];
    __shared__ float Bs[2][8][128];

    const int tid = threadIdx.x;
    const int bm = blockIdx.y * 128;
    const int bn = blockIdx.x * 128;

    const int aRow = tid >> 1;            // 0..127
    const int aCol = (tid & 1) * 4;       // 0 or 4
    const int bRow = tid >> 5;            // 0..7
    const int bCol = (tid & 31) * 4;      // 0..124

    const int tr = (tid >> 4) * 8;        // 0..120
    const int tc = (tid & 15) * 8;        // 0..120

    float acc[8][8];
    #pragma unroll
    for (int i = 0; i < 8; i++)
        #pragma unroll
        for (int j = 0; j < 8; j++) acc[i][j] = 0.0f;

    const float* Aptr = A + (size_t)(bm + aRow) * K + aCol;
    const float* Bptr = B + (size_t)bRow * N + bn + bCol;

    // Prologue: load tile 0 into buffer 0
    {
        float4 av = *(const float4*)(Aptr);
        As[0][aCol + 0][aRow] = av.x;
        As[0][aCol + 1][aRow] = av.y;
        As[0][aCol + 2][aRow] = av.z;
        As[0][aCol + 3][aRow] = av.w;
        float4 bv = *(const float4*)(Bptr);
        *(float4*)&Bs[0][bRow][bCol] = bv;
    }
    __syncthreads();

    int buf = 0;
    for (int k0 = 8; k0 <= K; k0 += 8) {
        float4 av, bv;
        const bool more = (k0 < K);
        if (more) {
            av = *(const float4*)(Aptr + k0);
            bv = *(const float4*)(Bptr + (size_t)k0 * N);
        }

        // Compute on current buffer while loads are in flight
        #pragma unroll
        for (int kk = 0; kk < 8; kk++) {
            float a[8], b[8];
            #pragma unroll
            for (int i = 0; i < 8; i++) a[i] = As[buf][kk][tr + i];
            #pragma unroll
            for (int j = 0; j < 8; j++) b[j] = Bs[buf][kk][tc + j];
            #pragma unroll
            for (int i = 0; i < 8; i++)
                #pragma unroll
                for (int j = 0; j < 8; j++)
                    acc[i][j] = fmaf(a[i], b[j], acc[i][j]);
        }

        if (more) {
            const int nb = buf ^ 1;
            As[nb][aCol + 0][aRow] = av.x;
            As[nb][aCol + 1][aRow] = av.y;
            As[nb][aCol + 2][aRow] = av.z;
            As[nb][aCol + 3][aRow] = av.w;
            *(float4*)&Bs[nb][bRow][bCol] = bv;
            __syncthreads();
            buf = nb;
        }
    }

    // Epilogue: bias + exact GELU, write to scratch
    #pragma unroll
    for (int i = 0; i < 8; i++) {
        const size_t row = (size_t)(bm + tr + i);
        #pragma unroll
        for (int j = 0; j < 8; j++) {
            const int col = bn + tc + j;
            float x = acc[i][j] + bias[col];
            float gel = 0.5f * x * (1.0f + erff(x * 0.7071067811865475f));
            g_h[row * HI + col] = gel;
        }
    }
}

// ---------------------------------------------------------------------------
// Kernel 2: in-place LayerNorm per row (eps = 1e-12), two-pass.
// ---------------------------------------------------------------------------
__device__ __forceinline__ float block_sum_256(float v, float* warp_red) {
    // warp reduce
    #pragma unroll
    for (int o = 16; o > 0; o >>= 1)
        v += __shfl_xor_sync(0xFFFFFFFFu, v, o);
    const int wid = threadIdx.x >> 5;
    const int lid = threadIdx.x & 31;
    if (lid == 0) warp_red[wid] = v;
    __syncthreads();
    float s = (lid < 8) ? warp_red[lid] : 0.0f;
    #pragma unroll
    for (int o = 4; o > 0; o >>= 1)
        s += __shfl_xor_sync(0xFFFFFFFFu, s, o);
    return __shfl_sync(0xFFFFFFFFu, s, 0);   // valid in every warp's lane pattern below
}

__global__ void __launch_bounds__(256)
ln_kernel(const float* __restrict__ g, const float* __restrict__ b) {
    __shared__ float row[HI];
    __shared__ float wr[8];
    __shared__ float s_mu, s_rstd;
    const int r = blockIdx.x;
    float* hp = g_h + (size_t)r * HI;
    const int t = threadIdx.x;

    float s = 0.0f;
    #pragma unroll
    for (int i = t; i < HI; i += 256) { float v = hp[i]; row[i] = v; s += v; }
    {
        #pragma unroll
        for (int o = 16; o > 0; o >>= 1) s += __shfl_xor_sync(0xFFFFFFFFu, s, o);
        if ((t & 31) == 0) wr[t >> 5] = s;
    }
    __syncthreads();
    if (t == 0) {
        float tot = 0.0f;
        #pragma unroll
        for (int w = 0; w < 8; w++) tot += wr[w];
        s_mu = tot * (1.0f / HI);
    }
    __syncthreads();
    const float mu = s_mu;

    float s2 = 0.0f;
    #pragma unroll
    for (int i = t; i < HI; i += 256) { float d = row[i] - mu; s2 = fmaf(d, d, s2); }
    {
        #pragma unroll
        for (int o = 16; o > 0; o >>= 1) s2 += __shfl_xor_sync(0xFFFFFFFFu, s2, o);
        if ((t & 31) == 0) wr[t >> 5] = s2;
    }
    __syncthreads();
    if (t == 0) {
        float tot = 0.0f;
        #pragma unroll
        for (int w = 0; w < 8; w++) tot += wr[w];
        s_rstd = rsqrtf(tot * (1.0f / HI) + 1e-12f);
    }
    __syncthreads();
    const float rstd = s_rstd;

    #pragma unroll
    for (int i = t; i < HI; i += 256)
        hp[i] = (row[i] - mu) * rstd * g[i] + b[i];
}

// ---------------------------------------------------------------------------
// Kernel 3: "own" rows — full 100-class logits for the 512 entity rows.
// VG_scores[e] = max softmax = 1 / sum(exp(l - lmax)); index = first argmax.
// Entity 511 publishes sel.
// ---------------------------------------------------------------------------
__global__ void __launch_bounds__(128)
own_kernel(const float* __restrict__ W2, const float* __restrict__ b2,
           float* __restrict__ out) {
    __shared__ float hs[HI];
    __shared__ float lg[DD];
    const int e = blockIdx.x;
    const int row = (e / EP) * ETOT + e;    // a = e//8 ; flat row = a*512 + e
    const float* hp = g_h + (size_t)row * HI;
    const int t = threadIdx.x;

    for (int i = t; i < HI; i += 128) hs[i] = hp[i];
    __syncthreads();

    if (t < DD) {
        float acc = b2[t];
        #pragma unroll 8
        for (int k = 0; k < HI; k++)
            acc = fmaf(hs[k], W2[(size_t)k * DD + t], acc);
        lg[t] = acc;
    }
    __syncthreads();

    if (t == 0) {
        float mx = lg[0]; int ix = 0;
        for (int d = 1; d < DD; d++)
            if (lg[d] > mx) { mx = lg[d]; ix = d; }
        float se = 0.0f;
        for (int d = 0; d < DD; d++) se += expf(lg[d] - mx);
        out[OFF_VGS + e] = 1.0f / se;
        out[OFF_IDX + e] = (float)ix;
        if (e == ETOT - 1) g_sel = ix;
    }
}

// ---------------------------------------------------------------------------
// Kernel 4: scores — one column (sel) of logits for all 32768 rows,
// each value replicated 8x (k axis) into scores[l,m,j,:].
// ---------------------------------------------------------------------------
__global__ void __launch_bounds__(128)
col_kernel(const float* __restrict__ W2, const float* __restrict__ b2,
           float* __restrict__ out) {
    __shared__ float wr[4];
    const int r = blockIdx.x;
    const int sel = g_sel;
    const float* hp = g_h + (size_t)r * HI;
    const int t = threadIdx.x;

    float s = 0.0f;
    #pragma unroll 4
    for (int k = t; k < HI; k += 128)
        s = fmaf(hp[k], W2[(size_t)k * DD + sel], s);
    #pragma unroll
    for (int o = 16; o > 0; o >>= 1)
        s += __shfl_xor_sync(0xFFFFFFFFu, s, o);
    if ((t & 31) == 0) wr[t >> 5] = s;
    __syncthreads();

    if (t == 0) {
        const float v = wr[0] + wr[1] + wr[2] + wr[3] + b2[sel];
        const int a = r >> 9;        // l = a
        const int e = r & 511;
        const int m = e >> 3;
        const int j = e & 7;
        const int base = (((a * AA) + m) * EP + j) * EP;   // 8-aligned
        float4 vv = make_float4(v, v, v, v);
        *(float4*)&out[OFF_SCORES + base]     = vv;
        *(float4*)&out[OFF_SCORES + base + 4] = vv;
    }
}

// ---------------------------------------------------------------------------
// Launch: inputs (metadata order): E, W1, b1, ln_g, ln_b, W2, b2, entity_count
// ---------------------------------------------------------------------------
extern "C" void kernel_launch(void* const* d_in, const int* in_sizes, int n_in,
                              void* d_out, int out_size) {
    const float* E    = (const float*)d_in[0];
    const float* W1   = (const float*)d_in[1];
    const float* b1   = (const float*)d_in[2];
    const float* ln_g = (const float*)d_in[3];
    const float* ln_b = (const float*)d_in[4];
    const float* W2   = (const float*)d_in[5];
    const float* b2   = (const float*)d_in[6];
    float* out = (float*)d_out;

    dim3 g1(HI / 128, MM / 128);          // (12, 256)
    gemm1_kernel<<<g1, 256>>>(E, W1, b1);
    ln_kernel<<<MM, 256>>>(ln_g, ln_b);
    own_kernel<<<ETOT, 128>>>(W2, b2, out);
    col_kernel<<<MM, 128>>>(W2, b2, out);
}

// round 6
// speedup vs baseline: 2.0835x; 2.0835x over previous
#include <cuda_runtime.h>
#include <cuda_bf16.h>
#include <math.h>
#include <stdint.h>

// ---------------- problem constants ----------------
#define AA    64
#define EP    8
#define ETOT  512
#define HH    768
#define HI    1536
#define DD    100
#define MM    32768
#define OFF_SCORES 0
#define OFF_VGS    262144
#define OFF_IDX    262656

// ---------------- scratch (no allocs allowed) ----------------
__device__ float          g_h[(size_t)MM * HI];          // GELU(E@W1+b1), pre-LN
__device__ __nv_bfloat16  g_e_hi[(size_t)MM * HH];       // E hi   [M][K]
__device__ __nv_bfloat16  g_e_lo[(size_t)MM * HH];       // E lo
__device__ __nv_bfloat16  g_w1t_hi[(size_t)HI * HH];     // W1^T hi [N][K]
__device__ __nv_bfloat16  g_w1t_lo[(size_t)HI * HH];     // W1^T lo
__device__ float          g_gw[HI];                      // ln_g[k] * W2[k,sel]
__device__ float          g_sgw;                         // sum ln_g*w
__device__ float          g_sbw;                         // sum ln_b*w + b2[sel]
__device__ int            g_sel;

// ---------------- helpers (base-family PTX only) ----------------
__device__ __forceinline__ uint32_t su32(const void* p) {
    uint32_t a;
    asm("{ .reg .u64 t; cvta.to.shared.u64 t, %1; cvt.u32.u64 %0, t; }"
        : "=r"(a) : "l"(p));
    return a;
}
#define CPA16(dst, src) \
    asm volatile("cp.async.cg.shared.global [%0], [%1], 16;" \
                 :: "r"(dst), "l"(src) : "memory")
#define CPA_COMMIT() asm volatile("cp.async.commit_group;" ::: "memory")
#define CPA_WAIT(n)  asm volatile("cp.async.wait_group %0;" :: "n"(n) : "memory")

#define LDSM4(r0, r1, r2, r3, addr) \
    asm volatile("ldmatrix.sync.aligned.m8n8.x4.shared.b16 {%0,%1,%2,%3}, [%4];" \
                 : "=r"(r0), "=r"(r1), "=r"(r2), "=r"(r3) : "r"(addr))

#define MMA16816(d, a0, a1, a2, a3, b0, b1) \
    asm volatile("mma.sync.aligned.m16n8k16.row.col.f32.bf16.bf16.f32 " \
                 "{%0,%1,%2,%3}, {%4,%5,%6,%7}, {%8,%9}, {%0,%1,%2,%3};" \
                 : "+f"((d)[0]), "+f"((d)[1]), "+f"((d)[2]), "+f"((d)[3]) \
                 : "r"(a0), "r"(a1), "r"(a2), "r"(a3), "r"(b0), "r"(b1))

__device__ __forceinline__ float gelu_exact(float x) {
    return 0.5f * x * (1.0f + erff(x * 0.7071067811865475f));
}

// ---------------- GEMM tile config ----------------
#define BM 128
#define BN 128
#define BK 64                     // bf16 elems -> 128B rows (SW128-style swizzle)
#define NCHUNK (HH / BK)          // 12
#define AHI 0
#define ALO 16384
#define BHI 32768
#define BLO 49152
#define STAGE 65536
#define DYN_SMEM (2 * STAGE)      // 128 KB

// ---------------------------------------------------------------------------
// prep_w1t: W1 [K][N] fp32 -> W1^T hi/lo bf16 [N][K]
// ---------------------------------------------------------------------------
__global__ void __launch_bounds__(1024)
prep_w1t_kernel(const float* __restrict__ W1) {
    __shared__ float tile[32][33];
    const int n0 = blockIdx.x * 32;
    const int k0 = blockIdx.y * 32;
    const int tx = threadIdx.x, ty = threadIdx.y;
    tile[ty][tx] = W1[(size_t)(k0 + ty) * HI + n0 + tx];
    __syncthreads();
    float x = tile[tx][ty];
    __nv_bfloat16 h = __float2bfloat16(x);
    __nv_bfloat16 l = __float2bfloat16(x - __bfloat162float(h));
    const size_t o = (size_t)(n0 + ty) * HH + k0 + tx;
    g_w1t_hi[o] = h;
    g_w1t_lo[o] = l;
}

// ---------------------------------------------------------------------------
// prep_e: E fp32 -> hi/lo bf16 (elementwise, same layout)
// ---------------------------------------------------------------------------
__global__ void __launch_bounds__(256)
prep_e_kernel(const float* __restrict__ E) {
    const size_t i = (size_t)blockIdx.x * 256 + threadIdx.x;   // x4 floats
    float4 v = ((const float4*)E)[i];
    __nv_bfloat16 h0 = __float2bfloat16(v.x);
    __nv_bfloat16 h1 = __float2bfloat16(v.y);
    __nv_bfloat16 h2 = __float2bfloat16(v.z);
    __nv_bfloat16 h3 = __float2bfloat16(v.w);
    __nv_bfloat162* H = (__nv_bfloat162*)g_e_hi;
    __nv_bfloat162* L = (__nv_bfloat162*)g_e_lo;
    H[i * 2]     = __halves2bfloat162(h0, h1);
    H[i * 2 + 1] = __halves2bfloat162(h2, h3);
    L[i * 2]     = __halves2bfloat162(__float2bfloat16(v.x - __bfloat162float(h0)),
                                      __float2bfloat16(v.y - __bfloat162float(h1)));
    L[i * 2 + 1] = __halves2bfloat162(__float2bfloat16(v.z - __bfloat162float(h2)),
                                      __float2bfloat16(v.w - __bfloat162float(h3)));
}

// ---------------------------------------------------------------------------
// GEMM: g_h = GELU(E @ W1 + b1) via mma.sync bf16 3-term split
// ---------------------------------------------------------------------------
__device__ __forceinline__ void cpa_stage(uint32_t smem_u, int buf, int bm,
                                          int bn, int k0, int tid) {
    const int row = tid >> 1;          // 0..127
    const int h   = tid & 1;           // half of 128B row
    const uint32_t st = smem_u + (uint32_t)buf * STAGE;
    const size_t asrc = (size_t)(bm + row) * HH + k0 + h * 32;
    const size_t bsrc = (size_t)(bn + row) * HH + k0 + h * 32;
    const __nv_bfloat16* ah = g_e_hi   + asrc;
    const __nv_bfloat16* al = g_e_lo   + asrc;
    const __nv_bfloat16* bh = g_w1t_hi + bsrc;
    const __nv_bfloat16* bl = g_w1t_lo + bsrc;
    const uint32_t dbase = (uint32_t)row * 128;
    const int s = row & 7;
    #pragma unroll
    for (int j = 0; j < 4; j++) {
        const int c = h * 4 + j;
        const uint32_t doff = dbase + (uint32_t)((c ^ s) * 16);
        CPA16(st + AHI + doff, ah + j * 8);
        CPA16(st + ALO + doff, al + j * 8);
        CPA16(st + BHI + doff, bh + j * 8);
        CPA16(st + BLO + doff, bl + j * 8);
    }
}

__global__ void __launch_bounds__(256, 1)
gemm_hmma_kernel(const float* __restrict__ b1) {
    extern __shared__ char smem[];
    const uint32_t smem_u = su32(smem);

    const int tid = threadIdx.x;
    const int w   = tid >> 5;
    const int l   = tid & 31;
    const int wm  = w >> 2;            // 0..1  (M)
    const int wn  = w & 3;             // 0..3  (N)
    const int bn  = blockIdx.x * BN;
    const int bm  = blockIdx.y * BM;

    float acc[4][4][4];
    #pragma unroll
    for (int i = 0; i < 4; i++)
        #pragma unroll
        for (int j = 0; j < 4; j++)
            #pragma unroll
            for (int k = 0; k < 4; k++) acc[i][j][k] = 0.0f;

    // lane-invariant ldmatrix address pieces
    const int mat  = l >> 3;           // 0..3
    const int rsub = l & 7;

    cpa_stage(smem_u, 0, bm, bn, 0, tid);
    CPA_COMMIT();

    for (int c = 0; c < NCHUNK; c++) {
        if (c + 1 < NCHUNK) {
            cpa_stage(smem_u, (c + 1) & 1, bm, bn, (c + 1) * BK, tid);
            CPA_COMMIT();
            CPA_WAIT(1);
        } else {
            CPA_WAIT(0);
        }
        __syncthreads();

        const uint32_t stg = smem_u + (uint32_t)(c & 1) * STAGE;
        const uint32_t aHi = stg + AHI, aLo = stg + ALO;
        const uint32_t bHi = stg + BHI, bLo = stg + BLO;

        #pragma unroll
        for (int ks = 0; ks < 4; ks++) {
            uint32_t af[4][4], bhr[2][4], blr[2][4];

            // A hi frags: 4 m16 tiles
            #pragma unroll
            for (int mi = 0; mi < 4; mi++) {
                const int row = wm * 64 + mi * 16 + ((mat & 1) << 3) + rsub;
                const int ch  = ks * 2 + (mat >> 1);
                const uint32_t ad = aHi + (uint32_t)(row * 128 + ((ch ^ (row & 7)) << 4));
                LDSM4(af[mi][0], af[mi][1], af[mi][2], af[mi][3], ad);
            }
            // B hi + lo frags: 2 x4 loads each (4 n8 tiles)
            #pragma unroll
            for (int np = 0; np < 2; np++) {
                const int row = wn * 32 + np * 16 + ((mat >> 1) << 3) + rsub;
                const int ch  = ks * 2 + (mat & 1);
                const uint32_t off = (uint32_t)(row * 128 + ((ch ^ (row & 7)) << 4));
                LDSM4(bhr[np][0], bhr[np][1], bhr[np][2], bhr[np][3], bHi + off);
                LDSM4(blr[np][0], blr[np][1], blr[np][2], blr[np][3], bLo + off);
            }
            // hi * hi
            #pragma unroll
            for (int mi = 0; mi < 4; mi++)
                #pragma unroll
                for (int ni = 0; ni < 4; ni++)
                    MMA16816(acc[mi][ni], af[mi][0], af[mi][1], af[mi][2], af[mi][3],
                             bhr[ni >> 1][(ni & 1) * 2], bhr[ni >> 1][(ni & 1) * 2 + 1]);
            // hi * lo
            #pragma unroll
            for (int mi = 0; mi < 4; mi++)
                #pragma unroll
                for (int ni = 0; ni < 4; ni++)
                    MMA16816(acc[mi][ni], af[mi][0], af[mi][1], af[mi][2], af[mi][3],
                             blr[ni >> 1][(ni & 1) * 2], blr[ni >> 1][(ni & 1) * 2 + 1]);
            // A lo frags (reuse af), then lo * hi
            #pragma unroll
            for (int mi = 0; mi < 4; mi++) {
                const int row = wm * 64 + mi * 16 + ((mat & 1) << 3) + rsub;
                const int ch  = ks * 2 + (mat >> 1);
                const uint32_t ad = aLo + (uint32_t)(row * 128 + ((ch ^ (row & 7)) << 4));
                LDSM4(af[mi][0], af[mi][1], af[mi][2], af[mi][3], ad);
            }
            #pragma unroll
            for (int mi = 0; mi < 4; mi++)
                #pragma unroll
                for (int ni = 0; ni < 4; ni++)
                    MMA16816(acc[mi][ni], af[mi][0], af[mi][1], af[mi][2], af[mi][3],
                             bhr[ni >> 1][(ni & 1) * 2], bhr[ni >> 1][(ni & 1) * 2 + 1]);
        }
        __syncthreads();
    }

    // Epilogue: bias + exact GELU -> g_h
    const int r0 = bm + wm * 64 + (l >> 2);
    const int c0 = bn + wn * 32 + (l & 3) * 2;
    #pragma unroll
    for (int mi = 0; mi < 4; mi++) {
        #pragma unroll
        for (int ni = 0; ni < 4; ni++) {
            const int row = r0 + mi * 16;
            const int col = c0 + ni * 8;
            const float2 bb = *(const float2*)(b1 + col);
            float2 o0, o1;
            o0.x = gelu_exact(acc[mi][ni][0] + bb.x);
            o0.y = gelu_exact(acc[mi][ni][1] + bb.y);
            o1.x = gelu_exact(acc[mi][ni][2] + bb.x);
            o1.y = gelu_exact(acc[mi][ni][3] + bb.y);
            *(float2*)(g_h + (size_t)row * HI + col)       = o0;
            *(float2*)(g_h + (size_t)(row + 8) * HI + col) = o1;
        }
    }
}

// ---------------------------------------------------------------------------
// own2: 512 entity rows -> exact two-pass LN -> 100 logits -> scores/idx/sel
// ---------------------------------------------------------------------------
__global__ void __launch_bounds__(128)
own2_kernel(const float* __restrict__ W2, const float* __restrict__ b2,
            const float* __restrict__ lg_, const float* __restrict__ lb_,
            float* __restrict__ out) {
    __shared__ float hs[HI];
    __shared__ float lg[DD];
    __shared__ float wr[4];
    __shared__ float s_mu, s_rstd;
    const int e = blockIdx.x;
    const int row = (e / EP) * ETOT + e;
    const float* hp = g_h + (size_t)row * HI;
    const int t = threadIdx.x;

    float s = 0.0f;
    #pragma unroll
    for (int i = t; i < HI; i += 128) { float v = hp[i]; hs[i] = v; s += v; }
    #pragma unroll
    for (int o = 16; o > 0; o >>= 1) s += __shfl_xor_sync(0xFFFFFFFFu, s, o);
    if ((t & 31) == 0) wr[t >> 5] = s;
    __syncthreads();
    if (t == 0) s_mu = (wr[0] + wr[1] + wr[2] + wr[3]) * (1.0f / HI);
    __syncthreads();
    const float mu = s_mu;

    float s2 = 0.0f;
    #pragma unroll
    for (int i = t; i < HI; i += 128) { float d = hs[i] - mu; s2 = fmaf(d, d, s2); }
    #pragma unroll
    for (int o = 16; o > 0; o >>= 1) s2 += __shfl_xor_sync(0xFFFFFFFFu, s2, o);
    if ((t & 31) == 0) wr[t >> 5] = s2;
    __syncthreads();
    if (t == 0) s_rstd = rsqrtf((wr[0] + wr[1] + wr[2] + wr[3]) * (1.0f / HI) + 1e-12f);
    __syncthreads();
    const float rstd = s_rstd;

    #pragma unroll
    for (int i = t; i < HI; i += 128)
        hs[i] = (hs[i] - mu) * rstd * lg_[i] + lb_[i];
    __syncthreads();

    if (t < DD) {
        float acc = b2[t];
        #pragma unroll 8
        for (int k = 0; k < HI; k++)
            acc = fmaf(hs[k], W2[(size_t)k * DD + t], acc);
        lg[t] = acc;
    }
    __syncthreads();

    if (t == 0) {
        float mx = lg[0]; int ix = 0;
        for (int d = 1; d < DD; d++)
            if (lg[d] > mx) { mx = lg[d]; ix = d; }
        float se = 0.0f;
        for (int d = 0; d < DD; d++) se += expf(lg[d] - mx);
        out[OFF_VGS + e] = 1.0f / se;
        out[OFF_IDX + e] = (float)ix;
        if (e == ETOT - 1) g_sel = ix;
    }
}

// ---------------------------------------------------------------------------
// prep2: gw[k] = ln_g[k]*W2[k,sel]; Sgw; Sbw = sum ln_b*w + b2[sel]
// ---------------------------------------------------------------------------
__global__ void __launch_bounds__(512)
prep2_kernel(const float* __restrict__ W2, const float* __restrict__ lg_,
             const float* __restrict__ lb_, const float* __restrict__ b2) {
    __shared__ float w1[16], w2s[16];
    const int t = threadIdx.x;
    const int sel = g_sel;
    float sg = 0.0f, sb = 0.0f;
    #pragma unroll
    for (int i = 0; i < 3; i++) {
        const int k = t + i * 512;
        const float w = W2[(size_t)k * DD + sel];
        const float gw = lg_[k] * w;
        g_gw[k] = gw;
        sg += gw;
        sb += lb_[k] * w;
    }
    #pragma unroll
    for (int o = 16; o > 0; o >>= 1) {
        sg += __shfl_xor_sync(0xFFFFFFFFu, sg, o);
        sb += __shfl_xor_sync(0xFFFFFFFFu, sb, o);
    }
    if ((t & 31) == 0) { w1[t >> 5] = sg; w2s[t >> 5] = sb; }
    __syncthreads();
    if (t == 0) {
        float a = 0.0f, b = 0.0f;
        #pragma unroll
        for (int w = 0; w < 16; w++) { a += w1[w]; b += w2s[w]; }
        g_sgw = a;
        g_sbw = b + b2[sel];
    }
}

// ---------------------------------------------------------------------------
// col2: fused LN + single-column dot per row; replicated 8x into scores
// ---------------------------------------------------------------------------
__global__ void __launch_bounds__(128)
col2_kernel(float* __restrict__ out) {
    __shared__ float r1[4], r2[4], r3[4];
    const int r = blockIdx.x;
    const int t = threadIdx.x;
    const float4* row = (const float4*)(g_h + (size_t)r * HI);
    const float4* gw  = (const float4*)g_gw;

    float s1 = 0.0f, s2 = 0.0f, sp = 0.0f;
    #pragma unroll
    for (int i = 0; i < 3; i++) {
        float4 v = row[t + i * 128];
        float4 w = gw[t + i * 128];
        s1 += (v.x + v.y) + (v.z + v.w);
        s2 = fmaf(v.x, v.x, fmaf(v.y, v.y, fmaf(v.z, v.z, fmaf(v.w, v.w, s2))));
        sp = fmaf(v.x, w.x, fmaf(v.y, w.y, fmaf(v.z, w.z, fmaf(v.w, w.w, sp))));
    }
    #pragma unroll
    for (int o = 16; o > 0; o >>= 1) {
        s1 += __shfl_xor_sync(0xFFFFFFFFu, s1, o);
        s2 += __shfl_xor_sync(0xFFFFFFFFu, s2, o);
        sp += __shfl_xor_sync(0xFFFFFFFFu, sp, o);
    }
    if ((t & 31) == 0) { r1[t >> 5] = s1; r2[t >> 5] = s2; r3[t >> 5] = sp; }
    __syncthreads();

    if (t == 0) {
        const float S1 = r1[0] + r1[1] + r1[2] + r1[3];
        const float S2 = r2[0] + r2[1] + r2[2] + r2[3];
        const float SP = r3[0] + r3[1] + r3[2] + r3[3];
        const float mu = S1 * (1.0f / HI);
        const float var = S2 * (1.0f / HI) - mu * mu;
        const float rstd = rsqrtf(var + 1e-12f);
        const float v = rstd * (SP - mu * g_sgw) + g_sbw;

        const int a = r >> 9;
        const int e = r & 511;
        const int m = e >> 3;
        const int j = e & 7;
        const int base = (((a * AA) + m) * EP + j) * EP;
        float4 vv = make_float4(v, v, v, v);
        *(float4*)&out[OFF_SCORES + base]     = vv;
        *(float4*)&out[OFF_SCORES + base + 4] = vv;
    }
}

// ---------------------------------------------------------------------------
// launch: E, W1, b1, ln_g, ln_b, W2, b2, entity_count
// ---------------------------------------------------------------------------
extern "C" void kernel_launch(void* const* d_in, const int* in_sizes, int n_in,
                              void* d_out, int out_size) {
    const float* E    = (const float*)d_in[0];
    const float* W1   = (const float*)d_in[1];
    const float* b1   = (const float*)d_in[2];
    const float* ln_g = (const float*)d_in[3];
    const float* ln_b = (const float*)d_in[4];
    const float* W2   = (const float*)d_in[5];
    const float* b2   = (const float*)d_in[6];
    float* out = (float*)d_out;

    cudaFuncSetAttribute(gemm_hmma_kernel,
                         cudaFuncAttributeMaxDynamicSharedMemorySize, DYN_SMEM);

    dim3 pb(32, 32);
    dim3 pg(HI / 32, HH / 32);                   // (48, 24)
    prep_w1t_kernel<<<pg, pb>>>(W1);
    prep_e_kernel<<<(MM * HH / 4) / 256, 256>>>(E);

    dim3 gg(HI / BN, MM / BM);                   // (12, 256)
    gemm_hmma_kernel<<<gg, 256, DYN_SMEM>>>(b1);

    own2_kernel<<<ETOT, 128>>>(W2, b2, ln_g, ln_b, out);
    prep2_kernel<<<1, 512>>>(W2, ln_g, ln_b, b2);
    col2_kernel<<<MM, 128>>>(out);
}

// round 7
// speedup vs baseline: 2.4109x; 1.1571x over previous
#include <cuda_runtime.h>
#include <cuda_bf16.h>
#include <math.h>
#include <stdint.h>

// ---------------- problem constants ----------------
#define AA    64
#define EP    8
#define ETOT  512
#define HH    768
#define HI    1536
#define DD    100
#define MM    32768
#define OFF_SCORES 0
#define OFF_VGS    262144
#define OFF_IDX    262656

// ---------------- scratch (no allocs allowed) ----------------
__device__ float          g_h[(size_t)MM * HI];          // GELU(E@W1+b1), pre-LN
__device__ __nv_bfloat16  g_e_hi[(size_t)MM * HH];       // E hi   [M][K]
__device__ __nv_bfloat16  g_e_lo[(size_t)MM * HH];       // E lo
__device__ __nv_bfloat16  g_w1t_hi[(size_t)HI * HH];     // W1^T hi [N][K]
__device__ __nv_bfloat16  g_w1t_lo[(size_t)HI * HH];     // W1^T lo
__device__ float          g_gw[HI];                      // ln_g[k] * W2[k,sel]
__device__ float          g_sgw;                         // sum ln_g*w
__device__ float          g_sbw;                         // sum ln_b*w + b2[sel]
__device__ int            g_sel;

// ---------------- helpers (base-family PTX only) ----------------
__device__ __forceinline__ uint32_t su32(const void* p) {
    uint32_t a;
    asm("{ .reg .u64 t; cvta.to.shared.u64 t, %1; cvt.u32.u64 %0, t; }"
        : "=r"(a) : "l"(p));
    return a;
}
#define CPA16(dst, src) \
    asm volatile("cp.async.cg.shared.global [%0], [%1], 16;" \
                 :: "r"(dst), "l"(src) : "memory")
#define CPA_COMMIT() asm volatile("cp.async.commit_group;" ::: "memory")
#define CPA_WAIT(n)  asm volatile("cp.async.wait_group %0;" :: "n"(n) : "memory")

#define LDSM4(r0, r1, r2, r3, addr) \
    asm volatile("ldmatrix.sync.aligned.m8n8.x4.shared.b16 {%0,%1,%2,%3}, [%4];" \
                 : "=r"(r0), "=r"(r1), "=r"(r2), "=r"(r3) : "r"(addr))

#define MMA16816(d, a0, a1, a2, a3, b0, b1) \
    asm volatile("mma.sync.aligned.m16n8k16.row.col.f32.bf16.bf16.f32 " \
                 "{%0,%1,%2,%3}, {%4,%5,%6,%7}, {%8,%9}, {%0,%1,%2,%3};" \
                 : "+f"((d)[0]), "+f"((d)[1]), "+f"((d)[2]), "+f"((d)[3]) \
                 : "r"(a0), "r"(a1), "r"(a2), "r"(a3), "r"(b0), "r"(b1))

__device__ __forceinline__ float gelu_exact(float x) {
    return 0.5f * x * (1.0f + erff(x * 0.7071067811865475f));
}

// ---------------- GEMM tile config ----------------
#define BM 256
#define BN 128
#define BK 64                     // bf16 elems -> 128B rows, XOR swizzle
#define NCHUNK (HH / BK)          // 12
#define AHI 0
#define ALO 32768
#define BHI 65536
#define BLO 81920
#define STAGE 98304               // 96 KB
#define DYN_SMEM (2 * STAGE)      // 192 KB

// ---------------------------------------------------------------------------
// prep_w1t: W1 [K][N] fp32 -> W1^T hi/lo bf16 [N][K]
// ---------------------------------------------------------------------------
__global__ void __launch_bounds__(1024)
prep_w1t_kernel(const float* __restrict__ W1) {
    __shared__ float tile[32][33];
    const int n0 = blockIdx.x * 32;
    const int k0 = blockIdx.y * 32;
    const int tx = threadIdx.x, ty = threadIdx.y;
    tile[ty][tx] = W1[(size_t)(k0 + ty) * HI + n0 + tx];
    __syncthreads();
    float x = tile[tx][ty];
    __nv_bfloat16 h = __float2bfloat16(x);
    __nv_bfloat16 l = __float2bfloat16(x - __bfloat162float(h));
    const size_t o = (size_t)(n0 + ty) * HH + k0 + tx;
    g_w1t_hi[o] = h;
    g_w1t_lo[o] = l;
}

// ---------------------------------------------------------------------------
// prep_e: E fp32 -> hi/lo bf16 (elementwise, same layout)
// ---------------------------------------------------------------------------
__global__ void __launch_bounds__(256)
prep_e_kernel(const float* __restrict__ E) {
    const size_t i = (size_t)blockIdx.x * 256 + threadIdx.x;   // x4 floats
    float4 v = ((const float4*)E)[i];
    __nv_bfloat16 h0 = __float2bfloat16(v.x);
    __nv_bfloat16 h1 = __float2bfloat16(v.y);
    __nv_bfloat16 h2 = __float2bfloat16(v.z);
    __nv_bfloat16 h3 = __float2bfloat16(v.w);
    __nv_bfloat162* H = (__nv_bfloat162*)g_e_hi;
    __nv_bfloat162* L = (__nv_bfloat162*)g_e_lo;
    H[i * 2]     = __halves2bfloat162(h0, h1);
    H[i * 2 + 1] = __halves2bfloat162(h2, h3);
    L[i * 2]     = __halves2bfloat162(__float2bfloat16(v.x - __bfloat162float(h0)),
                                      __float2bfloat16(v.y - __bfloat162float(h1)));
    L[i * 2 + 1] = __halves2bfloat162(__float2bfloat16(v.z - __bfloat162float(h2)),
                                      __float2bfloat16(v.w - __bfloat162float(h3)));
}

// ---------------------------------------------------------------------------
// GEMM: g_h = GELU(E @ W1 + b1) via mma.sync bf16 3-term split
// 512 threads: 16 warps = 4(M) x 4(N), warp tile 64x32.
// ---------------------------------------------------------------------------
__device__ __forceinline__ void cpa_stage(uint32_t smem_u, int buf, int bm,
                                          int bn, int k0, int tid) {
    const uint32_t st = smem_u + (uint32_t)buf * STAGE;
    // A: 256 rows x 64 bf16 (hi & lo). thread: row = tid>>1, half = tid&1
    {
        const int row = tid >> 1;
        const int h   = tid & 1;
        const size_t asrc = (size_t)(bm + row) * HH + k0 + h * 32;
        const __nv_bfloat16* ah = g_e_hi + asrc;
        const __nv_bfloat16* al = g_e_lo + asrc;
        const uint32_t dbase = (uint32_t)row * 128;
        const int s = row & 7;
        #pragma unroll
        for (int j = 0; j < 4; j++) {
            const int c = h * 4 + j;
            const uint32_t doff = dbase + (uint32_t)((c ^ s) * 16);
            CPA16(st + AHI + doff, ah + j * 8);
            CPA16(st + ALO + doff, al + j * 8);
        }
    }
    // B: 128 rows x 64 bf16 (hi & lo). thread: row = tid>>2, q = tid&3
    {
        const int row = tid >> 2;
        const int q   = tid & 3;
        const size_t bsrc = (size_t)(bn + row) * HH + k0 + q * 16;
        const __nv_bfloat16* bh = g_w1t_hi + bsrc;
        const __nv_bfloat16* bl = g_w1t_lo + bsrc;
        const uint32_t dbase = (uint32_t)row * 128;
        const int s = row & 7;
        #pragma unroll
        for (int j = 0; j < 2; j++) {
            const int c = q * 2 + j;
            const uint32_t doff = dbase + (uint32_t)((c ^ s) * 16);
            CPA16(st + BHI + doff, bh + j * 8);
            CPA16(st + BLO + doff, bl + j * 8);
        }
    }
}

__global__ void __launch_bounds__(512, 1)
gemm_hmma_kernel(const float* __restrict__ b1) {
    extern __shared__ char smem[];
    const uint32_t smem_u = su32(smem);

    const int tid = threadIdx.x;
    const int w   = tid >> 5;
    const int l   = tid & 31;
    const int wm  = w >> 2;            // 0..3  (M, 64 rows each)
    const int wn  = w & 3;             // 0..3  (N, 32 cols each)
    const int bn  = blockIdx.x * BN;
    const int bm  = blockIdx.y * BM;

    float acc[4][4][4];
    #pragma unroll
    for (int i = 0; i < 4; i++)
        #pragma unroll
        for (int j = 0; j < 4; j++)
            #pragma unroll
            for (int k = 0; k < 4; k++) acc[i][j][k] = 0.0f;

    const int mat  = l >> 3;           // 0..3
    const int rsub = l & 7;

    cpa_stage(smem_u, 0, bm, bn, 0, tid);
    CPA_COMMIT();

    for (int c = 0; c < NCHUNK; c++) {
        if (c + 1 < NCHUNK) {
            cpa_stage(smem_u, (c + 1) & 1, bm, bn, (c + 1) * BK, tid);
            CPA_COMMIT();
            CPA_WAIT(1);
        } else {
            CPA_WAIT(0);
        }
        __syncthreads();

        const uint32_t stg = smem_u + (uint32_t)(c & 1) * STAGE;
        const uint32_t aHi = stg + AHI, aLo = stg + ALO;
        const uint32_t bHi = stg + BHI, bLo = stg + BLO;

        #pragma unroll
        for (int ks = 0; ks < 4; ks++) {
            uint32_t af[4][4], bhr[2][4], blr[2][4];

            // A hi frags: 4 m16 tiles (warp rows wm*64 .. +63)
            #pragma unroll
            for (int mi = 0; mi < 4; mi++) {
                const int row = wm * 64 + mi * 16 + ((mat & 1) << 3) + rsub;
                const int ch  = ks * 2 + (mat >> 1);
                const uint32_t ad = aHi + (uint32_t)(row * 128 + ((ch ^ (row & 7)) << 4));
                LDSM4(af[mi][0], af[mi][1], af[mi][2], af[mi][3], ad);
            }
            // B hi + lo frags
            #pragma unroll
            for (int np = 0; np < 2; np++) {
                const int row = wn * 32 + np * 16 + ((mat >> 1) << 3) + rsub;
                const int ch  = ks * 2 + (mat & 1);
                const uint32_t off = (uint32_t)(row * 128 + ((ch ^ (row & 7)) << 4));
                LDSM4(bhr[np][0], bhr[np][1], bhr[np][2], bhr[np][3], bHi + off);
                LDSM4(blr[np][0], blr[np][1], blr[np][2], blr[np][3], bLo + off);
            }
            // hi * hi
            #pragma unroll
            for (int mi = 0; mi < 4; mi++)
                #pragma unroll
                for (int ni = 0; ni < 4; ni++)
                    MMA16816(acc[mi][ni], af[mi][0], af[mi][1], af[mi][2], af[mi][3],
                             bhr[ni >> 1][(ni & 1) * 2], bhr[ni >> 1][(ni & 1) * 2 + 1]);
            // hi * lo
            #pragma unroll
            for (int mi = 0; mi < 4; mi++)
                #pragma unroll
                for (int ni = 0; ni < 4; ni++)
                    MMA16816(acc[mi][ni], af[mi][0], af[mi][1], af[mi][2], af[mi][3],
                             blr[ni >> 1][(ni & 1) * 2], blr[ni >> 1][(ni & 1) * 2 + 1]);
            // A lo frags (reuse af), then lo * hi
            #pragma unroll
            for (int mi = 0; mi < 4; mi++) {
                const int row = wm * 64 + mi * 16 + ((mat & 1) << 3) + rsub;
                const int ch  = ks * 2 + (mat >> 1);
                const uint32_t ad = aLo + (uint32_t)(row * 128 + ((ch ^ (row & 7)) << 4));
                LDSM4(af[mi][0], af[mi][1], af[mi][2], af[mi][3], ad);
            }
            #pragma unroll
            for (int mi = 0; mi < 4; mi++)
                #pragma unroll
                for (int ni = 0; ni < 4; ni++)
                    MMA16816(acc[mi][ni], af[mi][0], af[mi][1], af[mi][2], af[mi][3],
                             bhr[ni >> 1][(ni & 1) * 2], bhr[ni >> 1][(ni & 1) * 2 + 1]);
        }
        __syncthreads();
    }

    // Epilogue: bias + exact GELU -> g_h
    const int r0 = bm + wm * 64 + (l >> 2);
    const int c0 = bn + wn * 32 + (l & 3) * 2;
    #pragma unroll
    for (int mi = 0; mi < 4; mi++) {
        #pragma unroll
        for (int ni = 0; ni < 4; ni++) {
            const int row = r0 + mi * 16;
            const int col = c0 + ni * 8;
            const float2 bb = *(const float2*)(b1 + col);
            float2 o0, o1;
            o0.x = gelu_exact(acc[mi][ni][0] + bb.x);
            o0.y = gelu_exact(acc[mi][ni][1] + bb.y);
            o1.x = gelu_exact(acc[mi][ni][2] + bb.x);
            o1.y = gelu_exact(acc[mi][ni][3] + bb.y);
            *(float2*)(g_h + (size_t)row * HI + col)       = o0;
            *(float2*)(g_h + (size_t)(row + 8) * HI + col) = o1;
        }
    }
}

// ---------------------------------------------------------------------------
// own2: 512 entity rows -> exact two-pass LN -> 100 logits -> scores/idx/sel
// 512 threads: logit dot split 4-way over k.
// ---------------------------------------------------------------------------
__global__ void __launch_bounds__(512)
own2_kernel(const float* __restrict__ W2, const float* __restrict__ b2,
            const float* __restrict__ lg_, const float* __restrict__ lb_,
            float* __restrict__ out) {
    __shared__ float hs[HI];
    __shared__ float part[4][128];
    __shared__ float lg[DD];
    __shared__ float wr[16];
    __shared__ float s_mu, s_rstd;
    const int e = blockIdx.x;
    const int row = (e / EP) * ETOT + e;
    const float* hp = g_h + (size_t)row * HI;
    const int t = threadIdx.x;

    float s = 0.0f;
    #pragma unroll
    for (int i = t; i < HI; i += 512) { float v = hp[i]; hs[i] = v; s += v; }
    #pragma unroll
    for (int o = 16; o > 0; o >>= 1) s += __shfl_xor_sync(0xFFFFFFFFu, s, o);
    if ((t & 31) == 0) wr[t >> 5] = s;
    __syncthreads();
    if (t == 0) {
        float tot = 0.0f;
        #pragma unroll
        for (int w = 0; w < 16; w++) tot += wr[w];
        s_mu = tot * (1.0f / HI);
    }
    __syncthreads();
    const float mu = s_mu;

    float s2 = 0.0f;
    #pragma unroll
    for (int i = t; i < HI; i += 512) { float d = hs[i] - mu; s2 = fmaf(d, d, s2); }
    #pragma unroll
    for (int o = 16; o > 0; o >>= 1) s2 += __shfl_xor_sync(0xFFFFFFFFu, s2, o);
    if ((t & 31) == 0) wr[t >> 5] = s2;
    __syncthreads();
    if (t == 0) {
        float tot = 0.0f;
        #pragma unroll
        for (int w = 0; w < 16; w++) tot += wr[w];
        s_rstd = rsqrtf(tot * (1.0f / HI) + 1e-12f);
    }
    __syncthreads();
    const float rstd = s_rstd;

    #pragma unroll
    for (int i = t; i < HI; i += 512)
        hs[i] = (hs[i] - mu) * rstd * lg_[i] + lb_[i];
    __syncthreads();

    // logits: seg = t>>7 owns k range [seg*384, seg*384+384)
    {
        const int seg = t >> 7;
        const int cls = t & 127;
        float acc = 0.0f;
        if (cls < DD) {
            const int k0 = seg * 384;
            #pragma unroll 8
            for (int k = k0; k < k0 + 384; k++)
                acc = fmaf(hs[k], W2[(size_t)k * DD + cls], acc);
        }
        part[seg][cls] = acc;
    }
    __syncthreads();
    if (t < DD)
        lg[t] = part[0][t] + part[1][t] + part[2][t] + part[3][t] + b2[t];
    __syncthreads();

    if (t == 0) {
        float mx = lg[0]; int ix = 0;
        for (int d = 1; d < DD; d++)
            if (lg[d] > mx) { mx = lg[d]; ix = d; }
        float se = 0.0f;
        for (int d = 0; d < DD; d++) se += expf(lg[d] - mx);
        out[OFF_VGS + e] = 1.0f / se;
        out[OFF_IDX + e] = (float)ix;
        if (e == ETOT - 1) g_sel = ix;
    }
}

// ---------------------------------------------------------------------------
// prep2: gw[k] = ln_g[k]*W2[k,sel]; Sgw; Sbw = sum ln_b*w + b2[sel]
// ---------------------------------------------------------------------------
__global__ void __launch_bounds__(512)
prep2_kernel(const float* __restrict__ W2, const float* __restrict__ lg_,
             const float* __restrict__ lb_, const float* __restrict__ b2) {
    __shared__ float w1[16], w2s[16];
    const int t = threadIdx.x;
    const int sel = g_sel;
    float sg = 0.0f, sb = 0.0f;
    #pragma unroll
    for (int i = 0; i < 3; i++) {
        const int k = t + i * 512;
        const float w = W2[(size_t)k * DD + sel];
        const float gw = lg_[k] * w;
        g_gw[k] = gw;
        sg += gw;
        sb += lb_[k] * w;
    }
    #pragma unroll
    for (int o = 16; o > 0; o >>= 1) {
        sg += __shfl_xor_sync(0xFFFFFFFFu, sg, o);
        sb += __shfl_xor_sync(0xFFFFFFFFu, sb, o);
    }
    if ((t & 31) == 0) { w1[t >> 5] = sg; w2s[t >> 5] = sb; }
    __syncthreads();
    if (t == 0) {
        float a = 0.0f, b = 0.0f;
        #pragma unroll
        for (int w = 0; w < 16; w++) { a += w1[w]; b += w2s[w]; }
        g_sgw = a;
        g_sbw = b + b2[sel];
    }
}

// ---------------------------------------------------------------------------
// col2: fused LN + single-column dot; 256 threads = 2 rows per block.
// ---------------------------------------------------------------------------
__global__ void __launch_bounds__(256)
col2_kernel(float* __restrict__ out) {
    __shared__ float r1[2][4], r2[2][4], r3[2][4];
    const int t  = threadIdx.x;
    const int gr = t >> 7;                 // row group 0/1
    const int tl = t & 127;
    const int r  = blockIdx.x * 2 + gr;
    const float4* row = (const float4*)(g_h + (size_t)r * HI);
    const float4* gw  = (const float4*)g_gw;

    float s1 = 0.0f, s2 = 0.0f, sp = 0.0f;
    #pragma unroll
    for (int i = 0; i < 3; i++) {
        float4 v = row[tl + i * 128];
        float4 w = gw[tl + i * 128];
        s1 += (v.x + v.y) + (v.z + v.w);
        s2 = fmaf(v.x, v.x, fmaf(v.y, v.y, fmaf(v.z, v.z, fmaf(v.w, v.w, s2))));
        sp = fmaf(v.x, w.x, fmaf(v.y, w.y, fmaf(v.z, w.z, fmaf(v.w, w.w, sp))));
    }
    #pragma unroll
    for (int o = 16; o > 0; o >>= 1) {
        s1 += __shfl_xor_sync(0xFFFFFFFFu, s1, o);
        s2 += __shfl_xor_sync(0xFFFFFFFFu, s2, o);
        sp += __shfl_xor_sync(0xFFFFFFFFu, sp, o);
    }
    if ((tl & 31) == 0) {
        const int w = tl >> 5;
        r1[gr][w] = s1; r2[gr][w] = s2; r3[gr][w] = sp;
    }
    __syncthreads();

    if (tl == 0) {
        const float S1 = r1[gr][0] + r1[gr][1] + r1[gr][2] + r1[gr][3];
        const float S2 = r2[gr][0] + r2[gr][1] + r2[gr][2] + r2[gr][3];
        const float SP = r3[gr][0] + r3[gr][1] + r3[gr][2] + r3[gr][3];
        const float mu = S1 * (1.0f / HI);
        const float var = S2 * (1.0f / HI) - mu * mu;
        const float rstd = rsqrtf(var + 1e-12f);
        const float v = rstd * (SP - mu * g_sgw) + g_sbw;

        const int a = r >> 9;
        const int e = r & 511;
        const int m = e >> 3;
        const int j = e & 7;
        const int base = (((a * AA) + m) * EP + j) * EP;
        float4 vv = make_float4(v, v, v, v);
        *(float4*)&out[OFF_SCORES + base]     = vv;
        *(float4*)&out[OFF_SCORES + base + 4] = vv;
    }
}

// ---------------------------------------------------------------------------
// launch: E, W1, b1, ln_g, ln_b, W2, b2, entity_count
// ---------------------------------------------------------------------------
extern "C" void kernel_launch(void* const* d_in, const int* in_sizes, int n_in,
                              void* d_out, int out_size) {
    const float* E    = (const float*)d_in[0];
    const float* W1   = (const float*)d_in[1];
    const float* b1   = (const float*)d_in[2];
    const float* ln_g = (const float*)d_in[3];
    const float* ln_b = (const float*)d_in[4];
    const float* W2   = (const float*)d_in[5];
    const float* b2   = (const float*)d_in[6];
    float* out = (float*)d_out;

    cudaFuncSetAttribute(gemm_hmma_kernel,
                         cudaFuncAttributeMaxDynamicSharedMemorySize, DYN_SMEM);

    dim3 pb(32, 32);
    dim3 pg(HI / 32, HH / 32);                   // (48, 24)
    prep_w1t_kernel<<<pg, pb>>>(W1);
    prep_e_kernel<<<(MM * HH / 4) / 256, 256>>>(E);

    dim3 gg(HI / BN, MM / BM);                   // (12, 128)
    gemm_hmma_kernel<<<gg, 512, DYN_SMEM>>>(b1);

    own2_kernel<<<ETOT, 512>>>(W2, b2, ln_g, ln_b, out);
    prep2_kernel<<<1, 512>>>(W2, ln_g, ln_b, b2);
    col2_kernel<<<MM / 2, 256>>>(out);
}

// round 9
// speedup vs baseline: 4.0254x; 1.6697x over previous
#include <cuda_runtime.h>
#include <cuda_fp16.h>
#include <math.h>
#include <stdint.h>

// ---------------- problem constants ----------------
#define AA    64
#define EP    8
#define ETOT  512
#define HH    768
#define HI    1536
#define DD    100
#define MM    32768
#define OFF_SCORES 0
#define OFF_VGS    262144
#define OFF_IDX    262656

// ---------------- scratch (no allocs allowed) ----------------
__device__ float   g_h[(size_t)MM * HI];        // GELU(E@W1+b1) fp16-accurate (for scores)
__device__ __half  g_e16[(size_t)MM * HH];      // E fp16 [M][K]
__device__ __half  g_w1t16[(size_t)HI * HH];    // W1^T fp16 [N][K]
__device__ float   g_eown[(size_t)ETOT * HH];   // gathered own rows of E (fp32)
__device__ float   g_hown[(size_t)ETOT * HI];   // exact GELU(E_own@W1+b1) fp32
__device__ float   g_gw[HI];                    // ln_g[k] * W2[k,sel]
__device__ float   g_sgw;
__device__ float   g_sbw;
__device__ int     g_sel;

// ---------------- helpers (base-family PTX only) ----------------
__device__ __forceinline__ uint32_t su32(const void* p) {
    uint32_t a;
    asm("{ .reg .u64 t; cvta.to.shared.u64 t, %1; cvt.u32.u64 %0, t; }"
        : "=r"(a) : "l"(p));
    return a;
}
#define CPA16(dst, src) \
    asm volatile("cp.async.cg.shared.global [%0], [%1], 16;" \
                 :: "r"(dst), "l"(src) : "memory")
#define CPA_COMMIT() asm volatile("cp.async.commit_group;" ::: "memory")
#define CPA_WAIT(n)  asm volatile("cp.async.wait_group %0;" :: "n"(n) : "memory")

#define LDSM4(r0, r1, r2, r3, addr) \
    asm volatile("ldmatrix.sync.aligned.m8n8.x4.shared.b16 {%0,%1,%2,%3}, [%4];" \
                 : "=r"(r0), "=r"(r1), "=r"(r2), "=r"(r3) : "r"(addr))

#define MMAF16(d, a0, a1, a2, a3, b0, b1) \
    asm volatile("mma.sync.aligned.m16n8k16.row.col.f32.f16.f16.f32 " \
                 "{%0,%1,%2,%3}, {%4,%5,%6,%7}, {%8,%9}, {%0,%1,%2,%3};" \
                 : "+f"((d)[0]), "+f"((d)[1]), "+f"((d)[2]), "+f"((d)[3]) \
                 : "r"(a0), "r"(a1), "r"(a2), "r"(a3), "r"(b0), "r"(b1))

__device__ __forceinline__ float gelu_exact(float x) {
    return 0.5f * x * (1.0f + erff(x * 0.7071067811865475f));
}

// ---------------- bulk GEMM tile config ----------------
#define BM 256
#define BN 128
#define BK 64                     // fp16 elems -> 128B rows, XOR swizzle
#define NCHUNK (HH / BK)          // 12
#define SA  0                     // A: 256*128B = 32 KB
#define SB  32768                 // B: 128*128B = 16 KB
#define STAGE 49152               // 48 KB
#define DYN_SMEM (2 * STAGE)      // 96 KB

// ---------------------------------------------------------------------------
// prep_w1t: W1 [K][N] fp32 -> W1^T fp16 [N][K]
// ---------------------------------------------------------------------------
__global__ void __launch_bounds__(1024)
prep_w1t_kernel(const float* __restrict__ W1) {
    __shared__ float tile[32][33];
    const int n0 = blockIdx.x * 32;
    const int k0 = blockIdx.y * 32;
    const int tx = threadIdx.x, ty = threadIdx.y;
    tile[ty][tx] = W1[(size_t)(k0 + ty) * HI + n0 + tx];
    __syncthreads();
    g_w1t16[(size_t)(n0 + ty) * HH + k0 + tx] = __float2half(tile[tx][ty]);
}

// ---------------------------------------------------------------------------
// prep_e: E fp32 -> fp16 (elementwise)
// ---------------------------------------------------------------------------
__global__ void __launch_bounds__(256)
prep_e_kernel(const float* __restrict__ E) {
    const size_t i = (size_t)blockIdx.x * 256 + threadIdx.x;   // x4 floats
    float4 v = ((const float4*)E)[i];
    __half2* H = (__half2*)g_e16;
    H[i * 2]     = __floats2half2_rn(v.x, v.y);
    H[i * 2 + 1] = __floats2half2_rn(v.z, v.w);
}

// ---------------------------------------------------------------------------
// gather_own: copy the 512 entity rows of E into compact fp32 buffer
// ---------------------------------------------------------------------------
__global__ void __launch_bounds__(192)
gather_own_kernel(const float* __restrict__ E) {
    const int e = blockIdx.x;
    const int row = (e / EP) * ETOT + e;
    const float4* src = (const float4*)(E + (size_t)row * HH);
    float4* dst = (float4*)(g_eown + (size_t)e * HH);
    dst[threadIdx.x] = src[threadIdx.x];
}

// ---------------------------------------------------------------------------
// bulk GEMM: g_h = GELU(E16 @ W1t16 + b1), 1-term fp16 HMMA
// 512 threads: 16 warps = 4(M) x 4(N), warp tile 64x32.
// ---------------------------------------------------------------------------
__device__ __forceinline__ void cpa_stage(uint32_t smem_u, int buf, int bm,
                                          int bn, int k0, int tid) {
    const uint32_t st = smem_u + (uint32_t)buf * STAGE;
    // A: 256 rows x 64 fp16. thread: row = tid>>1, half = tid&1 (4 chunks)
    {
        const int row = tid >> 1;
        const int h   = tid & 1;
        const __half* ap = g_e16 + (size_t)(bm + row) * HH + k0 + h * 32;
        const uint32_t dbase = (uint32_t)row * 128;
        const int s = row & 7;
        #pragma unroll
        for (int j = 0; j < 4; j++) {
            const int c = h * 4 + j;
            CPA16(st + SA + dbase + (uint32_t)((c ^ s) * 16), ap + j * 8);
        }
    }
    // B: 128 rows x 64 fp16. thread: row = tid>>2, q = tid&3 (2 chunks)
    {
        const int row = tid >> 2;
        const int q   = tid & 3;
        const __half* bp = g_w1t16 + (size_t)(bn + row) * HH + k0 + q * 16;
        const uint32_t dbase = (uint32_t)row * 128;
        const int s = row & 7;
        #pragma unroll
        for (int j = 0; j < 2; j++) {
            const int c = q * 2 + j;
            CPA16(st + SB + dbase + (uint32_t)((c ^ s) * 16), bp + j * 8);
        }
    }
}

__global__ void __launch_bounds__(512, 1)
gemm_hmma_kernel(const float* __restrict__ b1) {
    extern __shared__ char smem[];
    const uint32_t smem_u = su32(smem);

    const int tid = threadIdx.x;
    const int w   = tid >> 5;
    const int l   = tid & 31;
    const int wm  = w >> 2;            // 0..3  (M, 64 rows each)
    const int wn  = w & 3;             // 0..3  (N, 32 cols each)
    const int bn  = blockIdx.x * BN;
    const int bm  = blockIdx.y * BM;

    float acc[4][4][4];
    #pragma unroll
    for (int i = 0; i < 4; i++)
        #pragma unroll
        for (int j = 0; j < 4; j++)
            #pragma unroll
            for (int k = 0; k < 4; k++) acc[i][j][k] = 0.0f;

    const int mat  = l >> 3;
    const int rsub = l & 7;

    cpa_stage(smem_u, 0, bm, bn, 0, tid);
    CPA_COMMIT();

    for (int c = 0; c < NCHUNK; c++) {
        if (c + 1 < NCHUNK) {
            cpa_stage(smem_u, (c + 1) & 1, bm, bn, (c + 1) * BK, tid);
            CPA_COMMIT();
            CPA_WAIT(1);
        } else {
            CPA_WAIT(0);
        }
        __syncthreads();

        const uint32_t stg = smem_u + (uint32_t)(c & 1) * STAGE;
        const uint32_t aB = stg + SA, bB = stg + SB;

        #pragma unroll
        for (int ks = 0; ks < 4; ks++) {
            uint32_t af[4][4], bf[2][4];

            #pragma unroll
            for (int mi = 0; mi < 4; mi++) {
                const int row = wm * 64 + mi * 16 + ((mat & 1) << 3) + rsub;
                const int ch  = ks * 2 + (mat >> 1);
                const uint32_t ad = aB + (uint32_t)(row * 128 + ((ch ^ (row & 7)) << 4));
                LDSM4(af[mi][0], af[mi][1], af[mi][2], af[mi][3], ad);
            }
            #pragma unroll
            for (int np = 0; np < 2; np++) {
                const int row = wn * 32 + np * 16 + ((mat >> 1) << 3) + rsub;
                const int ch  = ks * 2 + (mat & 1);
                const uint32_t off = (uint32_t)(row * 128 + ((ch ^ (row & 7)) << 4));
                LDSM4(bf[np][0], bf[np][1], bf[np][2], bf[np][3], bB + off);
            }
            #pragma unroll
            for (int mi = 0; mi < 4; mi++)
                #pragma unroll
                for (int ni = 0; ni < 4; ni++)
                    MMAF16(acc[mi][ni], af[mi][0], af[mi][1], af[mi][2], af[mi][3],
                           bf[ni >> 1][(ni & 1) * 2], bf[ni >> 1][(ni & 1) * 2 + 1]);
        }
        __syncthreads();
    }

    // Epilogue: bias + exact GELU -> g_h
    const int r0 = bm + wm * 64 + (l >> 2);
    const int c0 = bn + wn * 32 + (l & 3) * 2;
    #pragma unroll
    for (int mi = 0; mi < 4; mi++) {
        #pragma unroll
        for (int ni = 0; ni < 4; ni++) {
            const int row = r0 + mi * 16;
            const int col = c0 + ni * 8;
            const float2 bb = *(const float2*)(b1 + col);
            float2 o0, o1;
            o0.x = gelu_exact(acc[mi][ni][0] + bb.x);
            o0.y = gelu_exact(acc[mi][ni][1] + bb.y);
            o1.x = gelu_exact(acc[mi][ni][2] + bb.x);
            o1.y = gelu_exact(acc[mi][ni][3] + bb.y);
            *(float2*)(g_h + (size_t)row * HI + col)       = o0;
            *(float2*)(g_h + (size_t)(row + 8) * HI + col) = o1;
        }
    }
}

// ---------------------------------------------------------------------------
// own_gemm: exact fp32  g_hown = GELU(g_eown @ W1 + b1)  [512 x 1536], K=768
// 64x64 tiles, BK=16, 256 threads, 4x4 per thread.
// ---------------------------------------------------------------------------
__global__ void __launch_bounds__(256)
own_gemm_kernel(const float* __restrict__ W1, const float* __restrict__ b1) {
    __shared__ float As[16][64];
    __shared__ float Bs[16][68];
    const int tid = threadIdx.x;
    const int bn = blockIdx.x * 64;
    const int bm = blockIdx.y * 64;
    const int tr = (tid >> 4) * 4;
    const int tc = (tid & 15) * 4;

    float acc[4][4];
    #pragma unroll
    for (int i = 0; i < 4; i++)
        #pragma unroll
        for (int j = 0; j < 4; j++) acc[i][j] = 0.0f;

    const int arow = tid >> 2;           // 0..63
    const int acol = (tid & 3) * 4;      // 0..12
    const int brow = tid >> 4;           // 0..15
    const int bcol = (tid & 15) * 4;     // 0..60

    for (int k0 = 0; k0 < HH; k0 += 16) {
        float4 av = *(const float4*)(g_eown + (size_t)(bm + arow) * HH + k0 + acol);
        As[acol + 0][arow] = av.x;
        As[acol + 1][arow] = av.y;
        As[acol + 2][arow] = av.z;
        As[acol + 3][arow] = av.w;
        float4 bv = *(const float4*)(W1 + (size_t)(k0 + brow) * HI + bn + bcol);
        *(float4*)&Bs[brow][bcol] = bv;
        __syncthreads();

        #pragma unroll
        for (int kk = 0; kk < 16; kk++) {
            float a[4], b[4];
            #pragma unroll
            for (int i = 0; i < 4; i++) a[i] = As[kk][tr + i];
            #pragma unroll
            for (int j = 0; j < 4; j++) b[j] = Bs[kk][tc + j];
            #pragma unroll
            for (int i = 0; i < 4; i++)
                #pragma unroll
                for (int j = 0; j < 4; j++)
                    acc[i][j] = fmaf(a[i], b[j], acc[i][j]);
        }
        __syncthreads();
    }

    #pragma unroll
    for (int i = 0; i < 4; i++) {
        #pragma unroll
        for (int j = 0; j < 4; j++) {
            const int col = bn + tc + j;
            g_hown[(size_t)(bm + tr + i) * HI + col] =
                gelu_exact(acc[i][j] + b1[col]);
        }
    }
}

// ---------------------------------------------------------------------------
// own2: exact LN + 100 logits + softmax-max/argmax per entity (from g_hown)
// ---------------------------------------------------------------------------
__global__ void __launch_bounds__(512)
own2_kernel(const float* __restrict__ W2, const float* __restrict__ b2,
            const float* __restrict__ lg_, const float* __restrict__ lb_,
            float* __restrict__ out) {
    __shared__ float hs[HI];
    __shared__ float part[4][128];
    __shared__ float lg[DD];
    __shared__ float wr[16];
    __shared__ float s_mu, s_rstd;
    const int e = blockIdx.x;
    const float* hp = g_hown + (size_t)e * HI;
    const int t = threadIdx.x;

    float s = 0.0f;
    #pragma unroll
    for (int i = t; i < HI; i += 512) { float v = hp[i]; hs[i] = v; s += v; }
    #pragma unroll
    for (int o = 16; o > 0; o >>= 1) s += __shfl_xor_sync(0xFFFFFFFFu, s, o);
    if ((t & 31) == 0) wr[t >> 5] = s;
    __syncthreads();
    if (t == 0) {
        float tot = 0.0f;
        #pragma unroll
        for (int w = 0; w < 16; w++) tot += wr[w];
        s_mu = tot * (1.0f / HI);
    }
    __syncthreads();
    const float mu = s_mu;

    float s2 = 0.0f;
    #pragma unroll
    for (int i = t; i < HI; i += 512) { float d = hs[i] - mu; s2 = fmaf(d, d, s2); }
    #pragma unroll
    for (int o = 16; o > 0; o >>= 1) s2 += __shfl_xor_sync(0xFFFFFFFFu, s2, o);
    if ((t & 31) == 0) wr[t >> 5] = s2;
    __syncthreads();
    if (t == 0) {
        float tot = 0.0f;
        #pragma unroll
        for (int w = 0; w < 16; w++) tot += wr[w];
        s_rstd = rsqrtf(tot * (1.0f / HI) + 1e-12f);
    }
    __syncthreads();
    const float rstd = s_rstd;

    #pragma unroll
    for (int i = t; i < HI; i += 512)
        hs[i] = (hs[i] - mu) * rstd * lg_[i] + lb_[i];
    __syncthreads();

    {
        const int seg = t >> 7;
        const int cls = t & 127;
        float acc = 0.0f;
        if (cls < DD) {
            const int k0 = seg * 384;
            #pragma unroll 8
            for (int k = k0; k < k0 + 384; k++)
                acc = fmaf(hs[k], W2[(size_t)k * DD + cls], acc);
        }
        part[seg][cls] = acc;
    }
    __syncthreads();
    if (t < DD)
        lg[t] = part[0][t] + part[1][t] + part[2][t] + part[3][t] + b2[t];
    __syncthreads();

    if (t == 0) {
        float mx = lg[0]; int ix = 0;
        for (int d = 1; d < DD; d++)
            if (lg[d] > mx) { mx = lg[d]; ix = d; }
        float se = 0.0f;
        for (int d = 0; d < DD; d++) se += expf(lg[d] - mx);
        out[OFF_VGS + e] = 1.0f / se;
        out[OFF_IDX + e] = (float)ix;
        if (e == ETOT - 1) g_sel = ix;
    }
}

// ---------------------------------------------------------------------------
// prep2: gw[k] = ln_g[k]*W2[k,sel]; Sgw; Sbw = sum ln_b*w + b2[sel]
// ---------------------------------------------------------------------------
__global__ void __launch_bounds__(512)
prep2_kernel(const float* __restrict__ W2, const float* __restrict__ lg_,
             const float* __restrict__ lb_, const float* __restrict__ b2) {
    __shared__ float w1[16], w2s[16];
    const int t = threadIdx.x;
    const int sel = g_sel;
    float sg = 0.0f, sb = 0.0f;
    #pragma unroll
    for (int i = 0; i < 3; i++) {
        const int k = t + i * 512;
        const float w = W2[(size_t)k * DD + sel];
        const float gw = lg_[k] * w;
        g_gw[k] = gw;
        sg += gw;
        sb += lb_[k] * w;
    }
    #pragma unroll
    for (int o = 16; o > 0; o >>= 1) {
        sg += __shfl_xor_sync(0xFFFFFFFFu, sg, o);
        sb += __shfl_xor_sync(0xFFFFFFFFu, sb, o);
    }
    if ((t & 31) == 0) { w1[t >> 5] = sg; w2s[t >> 5] = sb; }
    __syncthreads();
    if (t == 0) {
        float a = 0.0f, b = 0.0f;
        #pragma unroll
        for (int w = 0; w < 16; w++) { a += w1[w]; b += w2s[w]; }
        g_sgw = a;
        g_sbw = b + b2[sel];
    }
}

// ---------------------------------------------------------------------------
// col2: fused LN + single-column dot; 256 threads = 2 rows per block.
// ---------------------------------------------------------------------------
__global__ void __launch_bounds__(256)
col2_kernel(float* __restrict__ out) {
    __shared__ float r1[2][4], r2[2][4], r3[2][4];
    const int t  = threadIdx.x;
    const int gr = t >> 7;
    const int tl = t & 127;
    const int r  = blockIdx.x * 2 + gr;
    const float4* row = (const float4*)(g_h + (size_t)r * HI);
    const float4* gw  = (const float4*)g_gw;

    float s1 = 0.0f, s2 = 0.0f, sp = 0.0f;
    #pragma unroll
    for (int i = 0; i < 3; i++) {
        float4 v = row[tl + i * 128];
        float4 w = gw[tl + i * 128];
        s1 += (v.x + v.y) + (v.z + v.w);
        s2 = fmaf(v.x, v.x, fmaf(v.y, v.y, fmaf(v.z, v.z, fmaf(v.w, v.w, s2))));
        sp = fmaf(v.x, w.x, fmaf(v.y, w.y, fmaf(v.z, w.z, fmaf(v.w, w.w, sp))));
    }
    #pragma unroll
    for (int o = 16; o > 0; o >>= 1) {
        s1 += __shfl_xor_sync(0xFFFFFFFFu, s1, o);
        s2 += __shfl_xor_sync(0xFFFFFFFFu, s2, o);
        sp += __shfl_xor_sync(0xFFFFFFFFu, sp, o);
    }
    if ((tl & 31) == 0) {
        const int w = tl >> 5;
        r1[gr][w] = s1; r2[gr][w] = s2; r3[gr][w] = sp;
    }
    __syncthreads();

    if (tl == 0) {
        const float S1 = r1[gr][0] + r1[gr][1] + r1[gr][2] + r1[gr][3];
        const float S2 = r2[gr][0] + r2[gr][1] + r2[gr][2] + r2[gr][3];
        const float SP = r3[gr][0] + r3[gr][1] + r3[gr][2] + r3[gr][3];
        const float mu = S1 * (1.0f / HI);
        const float var = S2 * (1.0f / HI) - mu * mu;
        const float rstd = rsqrtf(var + 1e-12f);
        const float v = rstd * (SP - mu * g_sgw) + g_sbw;

        const int a = r >> 9;
        const int e = r & 511;
        const int m = e >> 3;
        const int j = e & 7;
        const int base = (((a * AA) + m) * EP + j) * EP;
        float4 vv = make_float4(v, v, v, v);
        *(float4*)&out[OFF_SCORES + base]     = vv;
        *(float4*)&out[OFF_SCORES + base + 4] = vv;
    }
}

// ---------------------------------------------------------------------------
// launch: E, W1, b1, ln_g, ln_b, W2, b2, entity_count
// ---------------------------------------------------------------------------
extern "C" void kernel_launch(void* const* d_in, const int* in_sizes, int n_in,
                              void* d_out, int out_size) {
    const float* E    = (const float*)d_in[0];
    const float* W1   = (const float*)d_in[1];
    const float* b1   = (const float*)d_in[2];
    const float* ln_g = (const float*)d_in[3];
    const float* ln_b = (const float*)d_in[4];
    const float* W2   = (const float*)d_in[5];
    const float* b2   = (const float*)d_in[6];
    float* out = (float*)d_out;

    cudaFuncSetAttribute(gemm_hmma_kernel,
                         cudaFuncAttributeMaxDynamicSharedMemorySize, DYN_SMEM);

    // prep (inputs only)
    dim3 pb(32, 32);
    dim3 pg(HI / 32, HH / 32);                   // (48, 24)
    prep_w1t_kernel<<<pg, pb>>>(W1);
    prep_e_kernel<<<(MM * HH / 4) / 256, 256>>>(E);
    gather_own_kernel<<<ETOT, 192>>>(E);

    // bulk fp16 path first (longest kernel starts ASAP in the stream)
    dim3 gg(HI / BN, MM / BM);                   // (12, 128)
    gemm_hmma_kernel<<<gg, 512, DYN_SMEM>>>(b1);

    // exact own-rows path
    dim3 og(HI / 64, ETOT / 64);                 // (24, 8)
    own_gemm_kernel<<<og, 256>>>(W1, b1);
    own2_kernel<<<ETOT, 512>>>(W2, b2, ln_g, ln_b, out);
    prep2_kernel<<<1, 512>>>(W2, ln_g, ln_b, b2);

    // scores
    col2_kernel<<<MM / 2, 256>>>(out);
}

// round 10
// speedup vs baseline: 4.1664x; 1.0350x over previous
#include <cuda_runtime.h>
#include <cuda_fp16.h>
#include <math.h>
#include <stdint.h>

// ---------------- problem constants ----------------
#define AA    64
#define EP    8
#define ETOT  512
#define HH    768
#define HI    1536
#define DD    100
#define MM    32768
#define OFF_SCORES 0
#define OFF_VGS    262144
#define OFF_IDX    262656

// ---------------- scratch (no allocs allowed) ----------------
__device__ __half  g_h16[(size_t)MM * HI];      // GELU(E@W1+b1) fp16 (scores path)
__device__ __half  g_e16[(size_t)MM * HH];      // E fp16 [M][K]
__device__ __half  g_w1t16[(size_t)HI * HH];    // W1^T fp16 [N][K]
__device__ float   g_eown[(size_t)ETOT * HH];   // gathered own rows of E (fp32)
__device__ float   g_hown[(size_t)ETOT * HI];   // exact GELU(E_own@W1+b1) fp32
__device__ float   g_gw[HI];                    // ln_g[k] * W2[k,sel]
__device__ float   g_sgw;
__device__ float   g_sbw;
__device__ int     g_sel;

// ---------------- helpers (base-family PTX only) ----------------
__device__ __forceinline__ uint32_t su32(const void* p) {
    uint32_t a;
    asm("{ .reg .u64 t; cvta.to.shared.u64 t, %1; cvt.u32.u64 %0, t; }"
        : "=r"(a) : "l"(p));
    return a;
}
#define CPA16(dst, src) \
    asm volatile("cp.async.cg.shared.global [%0], [%1], 16;" \
                 :: "r"(dst), "l"(src) : "memory")
#define CPA_COMMIT() asm volatile("cp.async.commit_group;" ::: "memory")
#define CPA_WAIT(n)  asm volatile("cp.async.wait_group %0;" :: "n"(n) : "memory")

#define LDSM4(r0, r1, r2, r3, addr) \
    asm volatile("ldmatrix.sync.aligned.m8n8.x4.shared.b16 {%0,%1,%2,%3}, [%4];" \
                 : "=r"(r0), "=r"(r1), "=r"(r2), "=r"(r3) : "r"(addr))

#define MMAF16(d, a0, a1, a2, a3, b0, b1) \
    asm volatile("mma.sync.aligned.m16n8k16.row.col.f32.f16.f16.f32 " \
                 "{%0,%1,%2,%3}, {%4,%5,%6,%7}, {%8,%9}, {%0,%1,%2,%3};" \
                 : "+f"((d)[0]), "+f"((d)[1]), "+f"((d)[2]), "+f"((d)[3]) \
                 : "r"(a0), "r"(a1), "r"(a2), "r"(a3), "r"(b0), "r"(b1))

__device__ __forceinline__ float gelu_exact(float x) {
    return 0.5f * x * (1.0f + erff(x * 0.7071067811865475f));
}

// ---------------- bulk GEMM tile config ----------------
#define BM 128
#define BN 128
#define BK 64                     // fp16 elems -> 128B rows, XOR swizzle
#define NCHUNK (HH / BK)          // 12
#define SA  0                     // A: 128*128B = 16 KB
#define SB  16384                 // B: 128*128B = 16 KB
#define STAGE 32768               // 32 KB
#define DYN_SMEM (2 * STAGE)      // 64 KB -> 2 CTAs/SM

// ---------------------------------------------------------------------------
// prep_w1t: W1 [K][N] fp32 -> W1^T fp16 [N][K]
// ---------------------------------------------------------------------------
__global__ void __launch_bounds__(1024)
prep_w1t_kernel(const float* __restrict__ W1) {
    __shared__ float tile[32][33];
    const int n0 = blockIdx.x * 32;
    const int k0 = blockIdx.y * 32;
    const int tx = threadIdx.x, ty = threadIdx.y;
    tile[ty][tx] = W1[(size_t)(k0 + ty) * HI + n0 + tx];
    __syncthreads();
    g_w1t16[(size_t)(n0 + ty) * HH + k0 + tx] = __float2half(tile[tx][ty]);
}

// ---------------------------------------------------------------------------
// prep_e: E fp32 -> fp16 (elementwise)
// ---------------------------------------------------------------------------
__global__ void __launch_bounds__(256)
prep_e_kernel(const float* __restrict__ E) {
    const size_t i = (size_t)blockIdx.x * 256 + threadIdx.x;   // x4 floats
    float4 v = ((const float4*)E)[i];
    __half2* H = (__half2*)g_e16;
    H[i * 2]     = __floats2half2_rn(v.x, v.y);
    H[i * 2 + 1] = __floats2half2_rn(v.z, v.w);
}

// ---------------------------------------------------------------------------
// gather_own: copy the 512 entity rows of E into compact fp32 buffer
// ---------------------------------------------------------------------------
__global__ void __launch_bounds__(192)
gather_own_kernel(const float* __restrict__ E) {
    const int e = blockIdx.x;
    const int row = (e / EP) * ETOT + e;
    const float4* src = (const float4*)(E + (size_t)row * HH);
    float4* dst = (float4*)(g_eown + (size_t)e * HH);
    dst[threadIdx.x] = src[threadIdx.x];
}

// ---------------------------------------------------------------------------
// bulk GEMM: g_h16 = GELU(E16 @ W1t16 + b1), 1-term fp16 HMMA
// 256 threads: 8 warps = 2(M) x 4(N), warp tile 64x32. 2 CTAs/SM.
// ---------------------------------------------------------------------------
__device__ __forceinline__ void cpa_stage(uint32_t smem_u, int buf, int bm,
                                          int bn, int k0, int tid) {
    const uint32_t st = smem_u + (uint32_t)buf * STAGE;
    const int row = tid >> 1;          // 0..127
    const int h   = tid & 1;           // half of 128B row
    const uint32_t dbase = (uint32_t)row * 128;
    const int s = row & 7;
    // A: 128 rows x 64 fp16
    {
        const __half* ap = g_e16 + (size_t)(bm + row) * HH + k0 + h * 32;
        #pragma unroll
        for (int j = 0; j < 4; j++) {
            const int c = h * 4 + j;
            CPA16(st + SA + dbase + (uint32_t)((c ^ s) * 16), ap + j * 8);
        }
    }
    // B: 128 rows x 64 fp16
    {
        const __half* bp = g_w1t16 + (size_t)(bn + row) * HH + k0 + h * 32;
        #pragma unroll
        for (int j = 0; j < 4; j++) {
            const int c = h * 4 + j;
            CPA16(st + SB + dbase + (uint32_t)((c ^ s) * 16), bp + j * 8);
        }
    }
}

__global__ void __launch_bounds__(256, 2)
gemm_hmma_kernel(const float* __restrict__ b1) {
    extern __shared__ char smem[];
    const uint32_t smem_u = su32(smem);

    const int tid = threadIdx.x;
    const int w   = tid >> 5;
    const int l   = tid & 31;
    const int wm  = w >> 2;            // 0..1  (M, 64 rows each)
    const int wn  = w & 3;             // 0..3  (N, 32 cols each)
    const int bn  = blockIdx.x * BN;
    const int bm  = blockIdx.y * BM;

    float acc[4][4][4];
    #pragma unroll
    for (int i = 0; i < 4; i++)
        #pragma unroll
        for (int j = 0; j < 4; j++)
            #pragma unroll
            for (int k = 0; k < 4; k++) acc[i][j][k] = 0.0f;

    const int mat  = l >> 3;
    const int rsub = l & 7;

    cpa_stage(smem_u, 0, bm, bn, 0, tid);
    CPA_COMMIT();

    for (int c = 0; c < NCHUNK; c++) {
        if (c + 1 < NCHUNK) {
            cpa_stage(smem_u, (c + 1) & 1, bm, bn, (c + 1) * BK, tid);
            CPA_COMMIT();
            CPA_WAIT(1);
        } else {
            CPA_WAIT(0);
        }
        __syncthreads();

        const uint32_t stg = smem_u + (uint32_t)(c & 1) * STAGE;
        const uint32_t aB = stg + SA, bB = stg + SB;

        #pragma unroll
        for (int ks = 0; ks < 4; ks++) {
            uint32_t af[4][4], bf[2][4];

            #pragma unroll
            for (int mi = 0; mi < 4; mi++) {
                const int row = wm * 64 + mi * 16 + ((mat & 1) << 3) + rsub;
                const int ch  = ks * 2 + (mat >> 1);
                const uint32_t ad = aB + (uint32_t)(row * 128 + ((ch ^ (row & 7)) << 4));
                LDSM4(af[mi][0], af[mi][1], af[mi][2], af[mi][3], ad);
            }
            #pragma unroll
            for (int np = 0; np < 2; np++) {
                const int row = wn * 32 + np * 16 + ((mat >> 1) << 3) + rsub;
                const int ch  = ks * 2 + (mat & 1);
                const uint32_t off = (uint32_t)(row * 128 + ((ch ^ (row & 7)) << 4));
                LDSM4(bf[np][0], bf[np][1], bf[np][2], bf[np][3], bB + off);
            }
            #pragma unroll
            for (int mi = 0; mi < 4; mi++)
                #pragma unroll
                for (int ni = 0; ni < 4; ni++)
                    MMAF16(acc[mi][ni], af[mi][0], af[mi][1], af[mi][2], af[mi][3],
                           bf[ni >> 1][(ni & 1) * 2], bf[ni >> 1][(ni & 1) * 2 + 1]);
        }
        __syncthreads();
    }

    // Epilogue: bias + exact GELU -> g_h16 (half2 stores)
    const int r0 = bm + wm * 64 + (l >> 2);
    const int c0 = bn + wn * 32 + (l & 3) * 2;
    #pragma unroll
    for (int mi = 0; mi < 4; mi++) {
        #pragma unroll
        for (int ni = 0; ni < 4; ni++) {
            const int row = r0 + mi * 16;
            const int col = c0 + ni * 8;
            const float2 bb = *(const float2*)(b1 + col);
            __half2 o0 = __floats2half2_rn(gelu_exact(acc[mi][ni][0] + bb.x),
                                           gelu_exact(acc[mi][ni][1] + bb.y));
            __half2 o1 = __floats2half2_rn(gelu_exact(acc[mi][ni][2] + bb.x),
                                           gelu_exact(acc[mi][ni][3] + bb.y));
            *(__half2*)(g_h16 + (size_t)row * HI + col)       = o0;
            *(__half2*)(g_h16 + (size_t)(row + 8) * HI + col) = o1;
        }
    }
}

// ---------------------------------------------------------------------------
// own_gemm: exact fp32  g_hown = GELU(g_eown @ W1 + b1)  [512 x 1536], K=768
// ---------------------------------------------------------------------------
__global__ void __launch_bounds__(256)
own_gemm_kernel(const float* __restrict__ W1, const float* __restrict__ b1) {
    __shared__ float As[16][64];
    __shared__ float Bs[16][68];
    const int tid = threadIdx.x;
    const int bn = blockIdx.x * 64;
    const int bm = blockIdx.y * 64;
    const int tr = (tid >> 4) * 4;
    const int tc = (tid & 15) * 4;

    float acc[4][4];
    #pragma unroll
    for (int i = 0; i < 4; i++)
        #pragma unroll
        for (int j = 0; j < 4; j++) acc[i][j] = 0.0f;

    const int arow = tid >> 2;
    const int acol = (tid & 3) * 4;
    const int brow = tid >> 4;
    const int bcol = (tid & 15) * 4;

    for (int k0 = 0; k0 < HH; k0 += 16) {
        float4 av = *(const float4*)(g_eown + (size_t)(bm + arow) * HH + k0 + acol);
        As[acol + 0][arow] = av.x;
        As[acol + 1][arow] = av.y;
        As[acol + 2][arow] = av.z;
        As[acol + 3][arow] = av.w;
        float4 bv = *(const float4*)(W1 + (size_t)(k0 + brow) * HI + bn + bcol);
        *(float4*)&Bs[brow][bcol] = bv;
        __syncthreads();

        #pragma unroll
        for (int kk = 0; kk < 16; kk++) {
            float a[4], b[4];
            #pragma unroll
            for (int i = 0; i < 4; i++) a[i] = As[kk][tr + i];
            #pragma unroll
            for (int j = 0; j < 4; j++) b[j] = Bs[kk][tc + j];
            #pragma unroll
            for (int i = 0; i < 4; i++)
                #pragma unroll
                for (int j = 0; j < 4; j++)
                    acc[i][j] = fmaf(a[i], b[j], acc[i][j]);
        }
        __syncthreads();
    }

    #pragma unroll
    for (int i = 0; i < 4; i++) {
        #pragma unroll
        for (int j = 0; j < 4; j++) {
            const int col = bn + tc + j;
            g_hown[(size_t)(bm + tr + i) * HI + col] =
                gelu_exact(acc[i][j] + b1[col]);
        }
    }
}

// ---------------------------------------------------------------------------
// own2: exact LN + 100 logits + softmax-max/argmax per entity (from g_hown)
// ---------------------------------------------------------------------------
__global__ void __launch_bounds__(512)
own2_kernel(const float* __restrict__ W2, const float* __restrict__ b2,
            const float* __restrict__ lg_, const float* __restrict__ lb_,
            float* __restrict__ out) {
    __shared__ float hs[HI];
    __shared__ float part[4][128];
    __shared__ float lg[DD];
    __shared__ float wr[16];
    __shared__ float s_mu, s_rstd;
    const int e = blockIdx.x;
    const float* hp = g_hown + (size_t)e * HI;
    const int t = threadIdx.x;

    float s = 0.0f;
    #pragma unroll
    for (int i = t; i < HI; i += 512) { float v = hp[i]; hs[i] = v; s += v; }
    #pragma unroll
    for (int o = 16; o > 0; o >>= 1) s += __shfl_xor_sync(0xFFFFFFFFu, s, o);
    if ((t & 31) == 0) wr[t >> 5] = s;
    __syncthreads();
    if (t == 0) {
        float tot = 0.0f;
        #pragma unroll
        for (int w = 0; w < 16; w++) tot += wr[w];
        s_mu = tot * (1.0f / HI);
    }
    __syncthreads();
    const float mu = s_mu;

    float s2 = 0.0f;
    #pragma unroll
    for (int i = t; i < HI; i += 512) { float d = hs[i] - mu; s2 = fmaf(d, d, s2); }
    #pragma unroll
    for (int o = 16; o > 0; o >>= 1) s2 += __shfl_xor_sync(0xFFFFFFFFu, s2, o);
    if ((t & 31) == 0) wr[t >> 5] = s2;
    __syncthreads();
    if (t == 0) {
        float tot = 0.0f;
        #pragma unroll
        for (int w = 0; w < 16; w++) tot += wr[w];
        s_rstd = rsqrtf(tot * (1.0f / HI) + 1e-12f);
    }
    __syncthreads();
    const float rstd = s_rstd;

    #pragma unroll
    for (int i = t; i < HI; i += 512)
        hs[i] = (hs[i] - mu) * rstd * lg_[i] + lb_[i];
    __syncthreads();

    {
        const int seg = t >> 7;
        const int cls = t & 127;
        float acc = 0.0f;
        if (cls < DD) {
            const int k0 = seg * 384;
            #pragma unroll 8
            for (int k = k0; k < k0 + 384; k++)
                acc = fmaf(hs[k], W2[(size_t)k * DD + cls], acc);
        }
        part[seg][cls] = acc;
    }
    __syncthreads();
    if (t < DD)
        lg[t] = part[0][t] + part[1][t] + part[2][t] + part[3][t] + b2[t];
    __syncthreads();

    if (t == 0) {
        float mx = lg[0]; int ix = 0;
        for (int d = 1; d < DD; d++)
            if (lg[d] > mx) { mx = lg[d]; ix = d; }
        float se = 0.0f;
        for (int d = 0; d < DD; d++) se += expf(lg[d] - mx);
        out[OFF_VGS + e] = 1.0f / se;
        out[OFF_IDX + e] = (float)ix;
        if (e == ETOT - 1) g_sel = ix;
    }
}

// ---------------------------------------------------------------------------
// prep2: gw[k] = ln_g[k]*W2[k,sel]; Sgw; Sbw = sum ln_b*w + b2[sel]
// ---------------------------------------------------------------------------
__global__ void __launch_bounds__(512)
prep2_kernel(const float* __restrict__ W2, const float* __restrict__ lg_,
             const float* __restrict__ lb_, const float* __restrict__ b2) {
    __shared__ float w1[16], w2s[16];
    const int t = threadIdx.x;
    const int sel = g_sel;
    float sg = 0.0f, sb = 0.0f;
    #pragma unroll
    for (int i = 0; i < 3; i++) {
        const int k = t + i * 512;
        const float w = W2[(size_t)k * DD + sel];
        const float gw = lg_[k] * w;
        g_gw[k] = gw;
        sg += gw;
        sb += lb_[k] * w;
    }
    #pragma unroll
    for (int o = 16; o > 0; o >>= 1) {
        sg += __shfl_xor_sync(0xFFFFFFFFu, sg, o);
        sb += __shfl_xor_sync(0xFFFFFFFFu, sb, o);
    }
    if ((t & 31) == 0) { w1[t >> 5] = sg; w2s[t >> 5] = sb; }
    __syncthreads();
    if (t == 0) {
        float a = 0.0f, b = 0.0f;
        #pragma unroll
        for (int w = 0; w < 16; w++) { a += w1[w]; b += w2s[w]; }
        g_sgw = a;
        g_sbw = b + b2[sel];
    }
}

// ---------------------------------------------------------------------------
// col2: fused LN + single-column dot from fp16 h; 2 rows per 256-thr block.
// ---------------------------------------------------------------------------
__global__ void __launch_bounds__(256)
col2_kernel(float* __restrict__ out) {
    __shared__ float r1[2][4], r2[2][4], r3[2][4];
    const int t  = threadIdx.x;
    const int gr = t >> 7;
    const int tl = t & 127;
    const int r  = blockIdx.x * 2 + gr;
    const __half2* row = (const __half2*)(g_h16 + (size_t)r * HI);
    const float2*  gw  = (const float2*)g_gw;

    float s1 = 0.0f, s2 = 0.0f, sp = 0.0f;
    #pragma unroll
    for (int i = 0; i < 6; i++) {
        const int idx = tl + i * 128;          // < 768
        float2 v = __half22float2(row[idx]);
        float2 w = gw[idx];
        s1 += v.x + v.y;
        s2 = fmaf(v.x, v.x, fmaf(v.y, v.y, s2));
        sp = fmaf(v.x, w.x, fmaf(v.y, w.y, sp));
    }
    #pragma unroll
    for (int o = 16; o > 0; o >>= 1) {
        s1 += __shfl_xor_sync(0xFFFFFFFFu, s1, o);
        s2 += __shfl_xor_sync(0xFFFFFFFFu, s2, o);
        sp += __shfl_xor_sync(0xFFFFFFFFu, sp, o);
    }
    if ((tl & 31) == 0) {
        const int w = tl >> 5;
        r1[gr][w] = s1; r2[gr][w] = s2; r3[gr][w] = sp;
    }
    __syncthreads();

    if (tl == 0) {
        const float S1 = r1[gr][0] + r1[gr][1] + r1[gr][2] + r1[gr][3];
        const float S2 = r2[gr][0] + r2[gr][1] + r2[gr][2] + r2[gr][3];
        const float SP = r3[gr][0] + r3[gr][1] + r3[gr][2] + r3[gr][3];
        const float mu = S1 * (1.0f / HI);
        const float var = S2 * (1.0f / HI) - mu * mu;
        const float rstd = rsqrtf(var + 1e-12f);
        const float v = rstd * (SP - mu * g_sgw) + g_sbw;

        const int a = r >> 9;
        const int e = r & 511;
        const int m = e >> 3;
        const int j = e & 7;
        const int base = (((a * AA) + m) * EP + j) * EP;
        float4 vv = make_float4(v, v, v, v);
        *(float4*)&out[OFF_SCORES + base]     = vv;
        *(float4*)&out[OFF_SCORES + base + 4] = vv;
    }
}

// ---------------------------------------------------------------------------
// launch: E, W1, b1, ln_g, ln_b, W2, b2, entity_count
// ---------------------------------------------------------------------------
extern "C" void kernel_launch(void* const* d_in, const int* in_sizes, int n_in,
                              void* d_out, int out_size) {
    const float* E    = (const float*)d_in[0];
    const float* W1   = (const float*)d_in[1];
    const float* b1   = (const float*)d_in[2];
    const float* ln_g = (const float*)d_in[3];
    const float* ln_b = (const float*)d_in[4];
    const float* W2   = (const float*)d_in[5];
    const float* b2   = (const float*)d_in[6];
    float* out = (float*)d_out;

    cudaFuncSetAttribute(gemm_hmma_kernel,
                         cudaFuncAttributeMaxDynamicSharedMemorySize, DYN_SMEM);

    // prep (inputs only)
    dim3 pb(32, 32);
    dim3 pg(HI / 32, HH / 32);                   // (48, 24)
    prep_w1t_kernel<<<pg, pb>>>(W1);
    prep_e_kernel<<<(MM * HH / 4) / 256, 256>>>(E);
    gather_own_kernel<<<ETOT, 192>>>(E);

    // bulk fp16 path first (longest kernel starts ASAP in the stream)
    dim3 gg(HI / BN, MM / BM);                   // (12, 256)
    gemm_hmma_kernel<<<gg, 256, DYN_SMEM>>>(b1);

    // exact own-rows path
    dim3 og(HI / 64, ETOT / 64);                 // (24, 8)
    own_gemm_kernel<<<og, 256>>>(W1, b1);
    own2_kernel<<<ETOT, 512>>>(W2, b2, ln_g, ln_b, out);
    prep2_kernel<<<1, 512>>>(W2, ln_g, ln_b, b2);

    // scores
    col2_kernel<<<MM / 2, 256>>>(out);
}

// round 11
// speedup vs baseline: 4.6518x; 1.1165x over previous
#include <cuda_runtime.h>
#include <cuda_fp16.h>
#include <math.h>
#include <stdint.h>

// ---------------- problem constants ----------------
#define AA    64
#define EP    8
#define ETOT  512
#define HH    768
#define HI    1536
#define DD    100
#define MM    32768
#define OFF_SCORES 0
#define OFF_VGS    262144
#define OFF_IDX    262656

// ---------------- scratch (no allocs allowed) ----------------
__device__ __half  g_e16[(size_t)MM * HH];      // E fp16 [M][K]
__device__ __half  g_w1t16[(size_t)HI * HH];    // W1^T fp16 [N][K]
__device__ float   g_eown[(size_t)ETOT * HH];   // gathered own rows of E (fp32)
__device__ float   g_hown[(size_t)ETOT * HI];   // exact GELU(E_own@W1+b1) fp32
__device__ float   g_gw[HI];                    // ln_g[k] * W2[k,sel]
__device__ float   g_s1[MM];                    // per-row sum h
__device__ float   g_s2[MM];                    // per-row sum h^2
__device__ float   g_sp[MM];                    // per-row sum h*gw
__device__ float   g_sgw;
__device__ float   g_sbw;
__device__ int     g_sel;

// ---------------- helpers (base-family PTX only) ----------------
__device__ __forceinline__ uint32_t su32(const void* p) {
    uint32_t a;
    asm("{ .reg .u64 t; cvta.to.shared.u64 t, %1; cvt.u32.u64 %0, t; }"
        : "=r"(a) : "l"(p));
    return a;
}
#define CPA16(dst, src) \
    asm volatile("cp.async.cg.shared.global [%0], [%1], 16;" \
                 :: "r"(dst), "l"(src) : "memory")
#define CPA_COMMIT() asm volatile("cp.async.commit_group;" ::: "memory")
#define CPA_WAIT(n)  asm volatile("cp.async.wait_group %0;" :: "n"(n) : "memory")

#define LDSM4(r0, r1, r2, r3, addr) \
    asm volatile("ldmatrix.sync.aligned.m8n8.x4.shared.b16 {%0,%1,%2,%3}, [%4];" \
                 : "=r"(r0), "=r"(r1), "=r"(r2), "=r"(r3) : "r"(addr))

#define MMAF16(d, a0, a1, a2, a3, b0, b1) \
    asm volatile("mma.sync.aligned.m16n8k16.row.col.f32.f16.f16.f32 " \
                 "{%0,%1,%2,%3}, {%4,%5,%6,%7}, {%8,%9}, {%0,%1,%2,%3};" \
                 : "+f"((d)[0]), "+f"((d)[1]), "+f"((d)[2]), "+f"((d)[3]) \
                 : "r"(a0), "r"(a1), "r"(a2), "r"(a3), "r"(b0), "r"(b1))

__device__ __forceinline__ float gelu_exact(float x) {
    return 0.5f * x * (1.0f + erff(x * 0.7071067811865475f));
}

// ---------------- bulk GEMM tile config ----------------
#define BM 128
#define BN 128
#define BK 64                     // fp16 elems -> 128B rows, XOR swizzle
#define NCHUNK (HH / BK)          // 12
#define SA  0                     // A: 128*128B = 16 KB
#define SB  16384                 // B: 128*128B = 16 KB
#define STAGE 32768               // 32 KB
#define NSTAGE 3
#define DYN_SMEM (NSTAGE * STAGE) // 96 KB -> 2 CTAs/SM

// ---------------------------------------------------------------------------
// prep_w1t: W1 [K][N] fp32 -> W1^T fp16 [N][K]
// ---------------------------------------------------------------------------
__global__ void __launch_bounds__(1024)
prep_w1t_kernel(const float* __restrict__ W1) {
    __shared__ float tile[32][33];
    const int n0 = blockIdx.x * 32;
    const int k0 = blockIdx.y * 32;
    const int tx = threadIdx.x, ty = threadIdx.y;
    tile[ty][tx] = W1[(size_t)(k0 + ty) * HI + n0 + tx];
    __syncthreads();
    g_w1t16[(size_t)(n0 + ty) * HH + k0 + tx] = __float2half(tile[tx][ty]);
}

// ---------------------------------------------------------------------------
// prep_e: E fp32 -> fp16 (elementwise)
// ---------------------------------------------------------------------------
__global__ void __launch_bounds__(256)
prep_e_kernel(const float* __restrict__ E) {
    const size_t i = (size_t)blockIdx.x * 256 + threadIdx.x;   // x4 floats
    float4 v = ((const float4*)E)[i];
    __half2* H = (__half2*)g_e16;
    H[i * 2]     = __floats2half2_rn(v.x, v.y);
    H[i * 2 + 1] = __floats2half2_rn(v.z, v.w);
}

// ---------------------------------------------------------------------------
// zero_red: clear the per-row reduction accumulators (every launch)
// ---------------------------------------------------------------------------
__global__ void __launch_bounds__(256)
zero_red_kernel() {
    const int i = blockIdx.x * 256 + threadIdx.x;   // < MM/4
    ((float4*)g_s1)[i] = make_float4(0.f, 0.f, 0.f, 0.f);
    ((float4*)g_s2)[i] = make_float4(0.f, 0.f, 0.f, 0.f);
    ((float4*)g_sp)[i] = make_float4(0.f, 0.f, 0.f, 0.f);
}

// ---------------------------------------------------------------------------
// gather_own: copy the 512 entity rows of E into compact fp32 buffer
// ---------------------------------------------------------------------------
__global__ void __launch_bounds__(192)
gather_own_kernel(const float* __restrict__ E) {
    const int e = blockIdx.x;
    const int row = (e / EP) * ETOT + e;
    const float4* src = (const float4*)(E + (size_t)row * HH);
    float4* dst = (float4*)(g_eown + (size_t)e * HH);
    dst[threadIdx.x] = src[threadIdx.x];
}

// ---------------------------------------------------------------------------
// bulk GEMM: reductions of GELU(E16 @ W1t16 + b1) fused into epilogue.
// 256 threads: 8 warps = 2(M) x 4(N), warp tile 64x32. 3-stage cp.async.
// ---------------------------------------------------------------------------
__device__ __forceinline__ void cpa_stage(uint32_t smem_u, int buf, int bm,
                                          int bn, int k0, int tid) {
    const uint32_t st = smem_u + (uint32_t)buf * STAGE;
    const int row = tid >> 1;
    const int h   = tid & 1;
    const uint32_t dbase = (uint32_t)row * 128;
    const int s = row & 7;
    {
        const __half* ap = g_e16 + (size_t)(bm + row) * HH + k0 + h * 32;
        #pragma unroll
        for (int j = 0; j < 4; j++) {
            const int c = h * 4 + j;
            CPA16(st + SA + dbase + (uint32_t)((c ^ s) * 16), ap + j * 8);
        }
    }
    {
        const __half* bp = g_w1t16 + (size_t)(bn + row) * HH + k0 + h * 32;
        #pragma unroll
        for (int j = 0; j < 4; j++) {
            const int c = h * 4 + j;
            CPA16(st + SB + dbase + (uint32_t)((c ^ s) * 16), bp + j * 8);
        }
    }
}

__global__ void __launch_bounds__(256, 2)
gemm_hmma_kernel(const float* __restrict__ b1) {
    extern __shared__ char smem[];
    const uint32_t smem_u = su32(smem);

    const int tid = threadIdx.x;
    const int w   = tid >> 5;
    const int l   = tid & 31;
    const int wm  = w >> 2;            // 0..1
    const int wn  = w & 3;             // 0..3
    const int bn  = blockIdx.x * BN;
    const int bm  = blockIdx.y * BM;

    float acc[4][4][4];
    #pragma unroll
    for (int i = 0; i < 4; i++)
        #pragma unroll
        for (int j = 0; j < 4; j++)
            #pragma unroll
            for (int k = 0; k < 4; k++) acc[i][j][k] = 0.0f;

    const int mat  = l >> 3;
    const int rsub = l & 7;

    cpa_stage(smem_u, 0, bm, bn, 0, tid);
    CPA_COMMIT();
    cpa_stage(smem_u, 1, bm, bn, BK, tid);
    CPA_COMMIT();

    int buf = 0;
    for (int c = 0; c < NCHUNK; c++) {
        if (c + 2 < NCHUNK) {
            cpa_stage(smem_u, (c + 2) % NSTAGE, bm, bn, (c + 2) * BK, tid);
            CPA_COMMIT();
            CPA_WAIT(2);
        } else if (c + 1 < NCHUNK) {
            CPA_WAIT(1);
        } else {
            CPA_WAIT(0);
        }
        __syncthreads();

        const uint32_t stg = smem_u + (uint32_t)buf * STAGE;
        const uint32_t aB = stg + SA, bB = stg + SB;

        #pragma unroll
        for (int ks = 0; ks < 4; ks++) {
            uint32_t af[4][4], bf[2][4];

            #pragma unroll
            for (int mi = 0; mi < 4; mi++) {
                const int row = wm * 64 + mi * 16 + ((mat & 1) << 3) + rsub;
                const int ch  = ks * 2 + (mat >> 1);
                const uint32_t ad = aB + (uint32_t)(row * 128 + ((ch ^ (row & 7)) << 4));
                LDSM4(af[mi][0], af[mi][1], af[mi][2], af[mi][3], ad);
            }
            #pragma unroll
            for (int np = 0; np < 2; np++) {
                const int row = wn * 32 + np * 16 + ((mat >> 1) << 3) + rsub;
                const int ch  = ks * 2 + (mat & 1);
                const uint32_t off = (uint32_t)(row * 128 + ((ch ^ (row & 7)) << 4));
                LDSM4(bf[np][0], bf[np][1], bf[np][2], bf[np][3], bB + off);
            }
            #pragma unroll
            for (int mi = 0; mi < 4; mi++)
                #pragma unroll
                for (int ni = 0; ni < 4; ni++)
                    MMAF16(acc[mi][ni], af[mi][0], af[mi][1], af[mi][2], af[mi][3],
                           bf[ni >> 1][(ni & 1) * 2], bf[ni >> 1][(ni & 1) * 2 + 1]);
        }
        __syncthreads();
        buf = (buf + 1) % NSTAGE;
    }

    // Epilogue: bias + exact GELU in fp32 regs, per-row S1/S2/SP reduction.
    const int r0 = bm + wm * 64 + (l >> 2);
    const int c0 = bn + wn * 32 + (l & 3) * 2;
    float2 gwv[4], bbv[4];
    #pragma unroll
    for (int ni = 0; ni < 4; ni++) {
        gwv[ni] = *(const float2*)(g_gw + c0 + ni * 8);
        bbv[ni] = *(const float2*)(b1 + c0 + ni * 8);
    }
    #pragma unroll
    for (int mi = 0; mi < 4; mi++) {
        #pragma unroll
        for (int hf = 0; hf < 2; hf++) {
            const int row = r0 + mi * 16 + hf * 8;
            float s1 = 0.0f, s2 = 0.0f, sp = 0.0f;
            #pragma unroll
            for (int ni = 0; ni < 4; ni++) {
                const float h0 = gelu_exact(acc[mi][ni][hf * 2 + 0] + bbv[ni].x);
                const float h1 = gelu_exact(acc[mi][ni][hf * 2 + 1] + bbv[ni].y);
                s1 += h0 + h1;
                s2 = fmaf(h0, h0, fmaf(h1, h1, s2));
                sp = fmaf(h0, gwv[ni].x, fmaf(h1, gwv[ni].y, sp));
            }
            // quad reduce (lanes sharing a row differ only in l&3)
            s1 += __shfl_xor_sync(0xFFFFFFFFu, s1, 1);
            s1 += __shfl_xor_sync(0xFFFFFFFFu, s1, 2);
            s2 += __shfl_xor_sync(0xFFFFFFFFu, s2, 1);
            s2 += __shfl_xor_sync(0xFFFFFFFFu, s2, 2);
            sp += __shfl_xor_sync(0xFFFFFFFFu, sp, 1);
            sp += __shfl_xor_sync(0xFFFFFFFFu, sp, 2);
            if ((l & 3) == 0) {
                atomicAdd(&g_s1[row], s1);
                atomicAdd(&g_s2[row], s2);
                atomicAdd(&g_sp[row], sp);
            }
        }
    }
}

// ---------------------------------------------------------------------------
// final: scores[row] from (S1,S2,SP); replicated 8x along k
// ---------------------------------------------------------------------------
__global__ void __launch_bounds__(256)
final_kernel(float* __restrict__ out) {
    const int r = blockIdx.x * 256 + threadIdx.x;   // < MM
    const float S1 = g_s1[r];
    const float S2 = g_s2[r];
    const float SP = g_sp[r];
    const float mu = S1 * (1.0f / HI);
    const float var = S2 * (1.0f / HI) - mu * mu;
    const float rstd = rsqrtf(var + 1e-12f);
    const float v = rstd * (SP - mu * g_sgw) + g_sbw;

    const int a = r >> 9;
    const int e = r & 511;
    const int m = e >> 3;
    const int j = e & 7;
    const int base = (((a * AA) + m) * EP + j) * EP;
    float4 vv = make_float4(v, v, v, v);
    *(float4*)&out[OFF_SCORES + base]     = vv;
    *(float4*)&out[OFF_SCORES + base + 4] = vv;
}

// ---------------------------------------------------------------------------
// own_gemm: exact fp32  g_hown = GELU(g_eown @ W1 + b1)  [512 x 1536], K=768
// ---------------------------------------------------------------------------
__global__ void __launch_bounds__(256)
own_gemm_kernel(const float* __restrict__ W1, const float* __restrict__ b1) {
    __shared__ float As[16][64];
    __shared__ float Bs[16][68];
    const int tid = threadIdx.x;
    const int bn = blockIdx.x * 64;
    const int bm = blockIdx.y * 64;
    const int tr = (tid >> 4) * 4;
    const int tc = (tid & 15) * 4;

    float acc[4][4];
    #pragma unroll
    for (int i = 0; i < 4; i++)
        #pragma unroll
        for (int j = 0; j < 4; j++) acc[i][j] = 0.0f;

    const int arow = tid >> 2;
    const int acol = (tid & 3) * 4;
    const int brow = tid >> 4;
    const int bcol = (tid & 15) * 4;

    for (int k0 = 0; k0 < HH; k0 += 16) {
        float4 av = *(const float4*)(g_eown + (size_t)(bm + arow) * HH + k0 + acol);
        As[acol + 0][arow] = av.x;
        As[acol + 1][arow] = av.y;
        As[acol + 2][arow] = av.z;
        As[acol + 3][arow] = av.w;
        float4 bv = *(const float4*)(W1 + (size_t)(k0 + brow) * HI + bn + bcol);
        *(float4*)&Bs[brow][bcol] = bv;
        __syncthreads();

        #pragma unroll
        for (int kk = 0; kk < 16; kk++) {
            float a[4], b[4];
            #pragma unroll
            for (int i = 0; i < 4; i++) a[i] = As[kk][tr + i];
            #pragma unroll
            for (int j = 0; j < 4; j++) b[j] = Bs[kk][tc + j];
            #pragma unroll
            for (int i = 0; i < 4; i++)
                #pragma unroll
                for (int j = 0; j < 4; j++)
                    acc[i][j] = fmaf(a[i], b[j], acc[i][j]);
        }
        __syncthreads();
    }

    #pragma unroll
    for (int i = 0; i < 4; i++) {
        #pragma unroll
        for (int j = 0; j < 4; j++) {
            const int col = bn + tc + j;
            g_hown[(size_t)(bm + tr + i) * HI + col] =
                gelu_exact(acc[i][j] + b1[col]);
        }
    }
}

// ---------------------------------------------------------------------------
// own2: exact LN + 100 logits + softmax-max/argmax per entity (from g_hown)
// ---------------------------------------------------------------------------
__global__ void __launch_bounds__(512)
own2_kernel(const float* __restrict__ W2, const float* __restrict__ b2,
            const float* __restrict__ lg_, const float* __restrict__ lb_,
            float* __restrict__ out) {
    __shared__ float hs[HI];
    __shared__ float part[4][128];
    __shared__ float lg[DD];
    __shared__ float wr[16];
    __shared__ float s_mu, s_rstd;
    const int e = blockIdx.x;
    const float* hp = g_hown + (size_t)e * HI;
    const int t = threadIdx.x;

    float s = 0.0f;
    #pragma unroll
    for (int i = t; i < HI; i += 512) { float v = hp[i]; hs[i] = v; s += v; }
    #pragma unroll
    for (int o = 16; o > 0; o >>= 1) s += __shfl_xor_sync(0xFFFFFFFFu, s, o);
    if ((t & 31) == 0) wr[t >> 5] = s;
    __syncthreads();
    if (t == 0) {
        float tot = 0.0f;
        #pragma unroll
        for (int w = 0; w < 16; w++) tot += wr[w];
        s_mu = tot * (1.0f / HI);
    }
    __syncthreads();
    const float mu = s_mu;

    float s2 = 0.0f;
    #pragma unroll
    for (int i = t; i < HI; i += 512) { float d = hs[i] - mu; s2 = fmaf(d, d, s2); }
    #pragma unroll
    for (int o = 16; o > 0; o >>= 1) s2 += __shfl_xor_sync(0xFFFFFFFFu, s2, o);
    if ((t & 31) == 0) wr[t >> 5] = s2;
    __syncthreads();
    if (t == 0) {
        float tot = 0.0f;
        #pragma unroll
        for (int w = 0; w < 16; w++) tot += wr[w];
        s_rstd = rsqrtf(tot * (1.0f / HI) + 1e-12f);
    }
    __syncthreads();
    const float rstd = s_rstd;

    #pragma unroll
    for (int i = t; i < HI; i += 512)
        hs[i] = (hs[i] - mu) * rstd * lg_[i] + lb_[i];
    __syncthreads();

    {
        const int seg = t >> 7;
        const int cls = t & 127;
        float acc = 0.0f;
        if (cls < DD) {
            const int k0 = seg * 384;
            #pragma unroll 8
            for (int k = k0; k < k0 + 384; k++)
                acc = fmaf(hs[k], W2[(size_t)k * DD + cls], acc);
        }
        part[seg][cls] = acc;
    }
    __syncthreads();
    if (t < DD)
        lg[t] = part[0][t] + part[1][t] + part[2][t] + part[3][t] + b2[t];
    __syncthreads();

    if (t == 0) {
        float mx = lg[0]; int ix = 0;
        for (int d = 1; d < DD; d++)
            if (lg[d] > mx) { mx = lg[d]; ix = d; }
        float se = 0.0f;
        for (int d = 0; d < DD; d++) se += expf(lg[d] - mx);
        out[OFF_VGS + e] = 1.0f / se;
        out[OFF_IDX + e] = (float)ix;
        if (e == ETOT - 1) g_sel = ix;
    }
}

// ---------------------------------------------------------------------------
// prep2: gw[k] = ln_g[k]*W2[k,sel]; Sgw; Sbw = sum ln_b*w + b2[sel]
// ---------------------------------------------------------------------------
__global__ void __launch_bounds__(512)
prep2_kernel(const float* __restrict__ W2, const float* __restrict__ lg_,
             const float* __restrict__ lb_, const float* __restrict__ b2) {
    __shared__ float w1[16], w2s[16];
    const int t = threadIdx.x;
    const int sel = g_sel;
    float sg = 0.0f, sb = 0.0f;
    #pragma unroll
    for (int i = 0; i < 3; i++) {
        const int k = t + i * 512;
        const float w = W2[(size_t)k * DD + sel];
        const float gw = lg_[k] * w;
        g_gw[k] = gw;
        sg += gw;
        sb += lb_[k] * w;
    }
    #pragma unroll
    for (int o = 16; o > 0; o >>= 1) {
        sg += __shfl_xor_sync(0xFFFFFFFFu, sg, o);
        sb += __shfl_xor_sync(0xFFFFFFFFu, sb, o);
    }
    if ((t & 31) == 0) { w1[t >> 5] = sg; w2s[t >> 5] = sb; }
    __syncthreads();
    if (t == 0) {
        float a = 0.0f, b = 0.0f;
        #pragma unroll
        for (int w = 0; w < 16; w++) { a += w1[w]; b += w2s[w]; }
        g_sgw = a;
        g_sbw = b + b2[sel];
    }
}

// ---------------------------------------------------------------------------
// launch: E, W1, b1, ln_g, ln_b, W2, b2, entity_count
// ---------------------------------------------------------------------------
extern "C" void kernel_launch(void* const* d_in, const int* in_sizes, int n_in,
                              void* d_out, int out_size) {
    const float* E    = (const float*)d_in[0];
    const float* W1   = (const float*)d_in[1];
    const float* b1   = (const float*)d_in[2];
    const float* ln_g = (const float*)d_in[3];
    const float* ln_b = (const float*)d_in[4];
    const float* W2   = (const float*)d_in[5];
    const float* b2   = (const float*)d_in[6];
    float* out = (float*)d_out;

    cudaFuncSetAttribute(gemm_hmma_kernel,
                         cudaFuncAttributeMaxDynamicSharedMemorySize, DYN_SMEM);

    // prep (inputs only)
    dim3 pb(32, 32);
    dim3 pg(HI / 32, HH / 32);                   // (48, 24)
    prep_w1t_kernel<<<pg, pb>>>(W1);
    prep_e_kernel<<<(MM * HH / 4) / 256, 256>>>(E);
    gather_own_kernel<<<ETOT, 192>>>(E);
    zero_red_kernel<<<(MM / 4) / 256, 256>>>();

    // exact own-rows path FIRST (produces sel -> g_gw for the fused epilogue)
    dim3 og(HI / 64, ETOT / 64);                 // (24, 8)
    own_gemm_kernel<<<og, 256>>>(W1, b1);
    own2_kernel<<<ETOT, 512>>>(W2, b2, ln_g, ln_b, out);
    prep2_kernel<<<1, 512>>>(W2, ln_g, ln_b, b2);

    // bulk fp16 path with fused per-row reductions
    dim3 gg(HI / BN, MM / BM);                   // (12, 256)
    gemm_hmma_kernel<<<gg, 256, DYN_SMEM>>>(b1);

    // scores from reductions
    final_kernel<<<MM / 256, 256>>>(out);
}

// round 12
// speedup vs baseline: 4.6804x; 1.0062x over previous
#include <cuda_runtime.h>
#include <cuda_fp16.h>
#include <math.h>
#include <stdint.h>

// ---------------- problem constants ----------------
#define AA    64
#define EP    8
#define ETOT  512
#define HH    768
#define HI    1536
#define DD    100
#define MM    32768
#define OFF_SCORES 0
#define OFF_VGS    262144
#define OFF_IDX    262656

// ---------------- scratch (no allocs allowed) ----------------
__device__ __half  g_e16[(size_t)MM * HH];      // E fp16 [M][K]
__device__ __half  g_w1t16[(size_t)HI * HH];    // W1^T fp16 [N][K]
__device__ float   g_hown[(size_t)ETOT * HI];   // exact GELU(E_own@W1+b1) fp32
__device__ float   g_gw[HI];                    // ln_g[k] * W2[k,sel]
__device__ float   g_s1[MM];                    // per-row sum h
__device__ float   g_s2[MM];                    // per-row sum h^2
__device__ float   g_sp[MM];                    // per-row sum h*gw
__device__ float   g_sgw;
__device__ float   g_sbw;

// ---------------- helpers (base-family PTX only) ----------------
__device__ __forceinline__ uint32_t su32(const void* p) {
    uint32_t a;
    asm("{ .reg .u64 t; cvta.to.shared.u64 t, %1; cvt.u32.u64 %0, t; }"
        : "=r"(a) : "l"(p));
    return a;
}
#define CPA16(dst, src) \
    asm volatile("cp.async.cg.shared.global [%0], [%1], 16;" \
                 :: "r"(dst), "l"(src) : "memory")
#define CPA_COMMIT() asm volatile("cp.async.commit_group;" ::: "memory")
#define CPA_WAIT(n)  asm volatile("cp.async.wait_group %0;" :: "n"(n) : "memory")

#define LDSM4(r0, r1, r2, r3, addr) \
    asm volatile("ldmatrix.sync.aligned.m8n8.x4.shared.b16 {%0,%1,%2,%3}, [%4];" \
                 : "=r"(r0), "=r"(r1), "=r"(r2), "=r"(r3) : "r"(addr))

#define MMAF16(d, a0, a1, a2, a3, b0, b1) \
    asm volatile("mma.sync.aligned.m16n8k16.row.col.f32.f16.f16.f32 " \
                 "{%0,%1,%2,%3}, {%4,%5,%6,%7}, {%8,%9}, {%0,%1,%2,%3};" \
                 : "+f"((d)[0]), "+f"((d)[1]), "+f"((d)[2]), "+f"((d)[3]) \
                 : "r"(a0), "r"(a1), "r"(a2), "r"(a3), "r"(b0), "r"(b1))

__device__ __forceinline__ float gelu_exact(float x) {
    return 0.5f * x * (1.0f + erff(x * 0.7071067811865475f));
}

// ---------------- bulk GEMM tile config ----------------
#define BM 64
#define BN 128
#define BK 64                     // fp16 elems -> 128B rows, XOR swizzle
#define NCHUNK (HH / BK)          // 12
#define SA  0                     // A: 64*128B  = 8 KB
#define SB  8192                  // B: 128*128B = 16 KB
#define STAGE 24576               // 24 KB
#define NSTAGE 3
#define DYN_SMEM (NSTAGE * STAGE) // 72 KB -> 3 CTAs/SM

// ---------------------------------------------------------------------------
// prep_w1t: W1 [K][N] fp32 -> W1^T fp16 [N][K]
// ---------------------------------------------------------------------------
__global__ void __launch_bounds__(1024)
prep_w1t_kernel(const float* __restrict__ W1) {
    __shared__ float tile[32][33];
    const int n0 = blockIdx.x * 32;
    const int k0 = blockIdx.y * 32;
    const int tx = threadIdx.x, ty = threadIdx.y;
    tile[ty][tx] = W1[(size_t)(k0 + ty) * HI + n0 + tx];
    __syncthreads();
    g_w1t16[(size_t)(n0 + ty) * HH + k0 + tx] = __float2half(tile[tx][ty]);
}

// ---------------------------------------------------------------------------
// prep_e: E fp32 -> fp16; also zeroes the per-row reduction accumulators
// ---------------------------------------------------------------------------
__global__ void __launch_bounds__(256)
prep_e_kernel(const float* __restrict__ E) {
    const size_t i = (size_t)blockIdx.x * 256 + threadIdx.x;   // x4 floats
    float4 v = ((const float4*)E)[i];
    __half2* H = (__half2*)g_e16;
    H[i * 2]     = __floats2half2_rn(v.x, v.y);
    H[i * 2 + 1] = __floats2half2_rn(v.z, v.w);
    if (i < MM / 4) {
        const float4 z = make_float4(0.f, 0.f, 0.f, 0.f);
        ((float4*)g_s1)[i] = z;
        ((float4*)g_s2)[i] = z;
        ((float4*)g_sp)[i] = z;
    }
}

// ---------------------------------------------------------------------------
// bulk GEMM: reductions of GELU(E16 @ W1t16 + b1) fused into epilogue.
// 256 threads: 8 warps = 2(M) x 4(N), warp tile 32x32. 3 CTAs/SM.
// ---------------------------------------------------------------------------
__device__ __forceinline__ void cpa_stage(uint32_t smem_u, int buf, int bm,
                                          int bn, int k0, int tid) {
    const uint32_t st = smem_u + (uint32_t)buf * STAGE;
    // A: 64 rows x 64 fp16. thread: row = tid>>2, q = tid&3 (2 chunks)
    {
        const int row = tid >> 2;
        const int q   = tid & 3;
        const __half* ap = g_e16 + (size_t)(bm + row) * HH + k0 + q * 16;
        const uint32_t dbase = (uint32_t)row * 128;
        const int s = row & 7;
        #pragma unroll
        for (int j = 0; j < 2; j++) {
            const int c = q * 2 + j;
            CPA16(st + SA + dbase + (uint32_t)((c ^ s) * 16), ap + j * 8);
        }
    }
    // B: 128 rows x 64 fp16. thread: row = tid>>1, h = tid&1 (4 chunks)
    {
        const int row = tid >> 1;
        const int h   = tid & 1;
        const __half* bp = g_w1t16 + (size_t)(bn + row) * HH + k0 + h * 32;
        const uint32_t dbase = (uint32_t)row * 128;
        const int s = row & 7;
        #pragma unroll
        for (int j = 0; j < 4; j++) {
            const int c = h * 4 + j;
            CPA16(st + SB + dbase + (uint32_t)((c ^ s) * 16), bp + j * 8);
        }
    }
}

__global__ void __launch_bounds__(256, 3)
gemm_hmma_kernel(const float* __restrict__ b1) {
    extern __shared__ char smem[];
    const uint32_t smem_u = su32(smem);

    const int tid = threadIdx.x;
    const int w   = tid >> 5;
    const int l   = tid & 31;
    const int wm  = w >> 2;            // 0..1  (M, 32 rows each)
    const int wn  = w & 3;             // 0..3  (N, 32 cols each)
    const int bn  = blockIdx.x * BN;
    const int bm  = blockIdx.y * BM;

    float acc[2][4][4];
    #pragma unroll
    for (int i = 0; i < 2; i++)
        #pragma unroll
        for (int j = 0; j < 4; j++)
            #pragma unroll
            for (int k = 0; k < 4; k++) acc[i][j][k] = 0.0f;

    const int mat  = l >> 3;
    const int rsub = l & 7;

    cpa_stage(smem_u, 0, bm, bn, 0, tid);
    CPA_COMMIT();
    cpa_stage(smem_u, 1, bm, bn, BK, tid);
    CPA_COMMIT();

    int buf = 0;
    for (int c = 0; c < NCHUNK; c++) {
        if (c + 2 < NCHUNK) {
            cpa_stage(smem_u, (c + 2) % NSTAGE, bm, bn, (c + 2) * BK, tid);
            CPA_COMMIT();
            CPA_WAIT(2);
        } else if (c + 1 < NCHUNK) {
            CPA_WAIT(1);
        } else {
            CPA_WAIT(0);
        }
        __syncthreads();

        const uint32_t stg = smem_u + (uint32_t)buf * STAGE;
        const uint32_t aB = stg + SA, bB = stg + SB;

        #pragma unroll
        for (int ks = 0; ks < 4; ks++) {
            uint32_t af[2][4], bf[2][4];

            #pragma unroll
            for (int mi = 0; mi < 2; mi++) {
                const int row = wm * 32 + mi * 16 + ((mat & 1) << 3) + rsub;
                const int ch  = ks * 2 + (mat >> 1);
                const uint32_t ad = aB + (uint32_t)(row * 128 + ((ch ^ (row & 7)) << 4));
                LDSM4(af[mi][0], af[mi][1], af[mi][2], af[mi][3], ad);
            }
            #pragma unroll
            for (int np = 0; np < 2; np++) {
                const int row = wn * 32 + np * 16 + ((mat >> 1) << 3) + rsub;
                const int ch  = ks * 2 + (mat & 1);
                const uint32_t off = (uint32_t)(row * 128 + ((ch ^ (row & 7)) << 4));
                LDSM4(bf[np][0], bf[np][1], bf[np][2], bf[np][3], bB + off);
            }
            #pragma unroll
            for (int mi = 0; mi < 2; mi++)
                #pragma unroll
                for (int ni = 0; ni < 4; ni++)
                    MMAF16(acc[mi][ni], af[mi][0], af[mi][1], af[mi][2], af[mi][3],
                           bf[ni >> 1][(ni & 1) * 2], bf[ni >> 1][(ni & 1) * 2 + 1]);
        }
        __syncthreads();
        buf = (buf + 1) % NSTAGE;
    }

    // Epilogue: bias + exact GELU in fp32 regs, per-row S1/S2/SP reduction.
    const int r0 = bm + wm * 32 + (l >> 2);
    const int c0 = bn + wn * 32 + (l & 3) * 2;
    float2 gwv[4], bbv[4];
    #pragma unroll
    for (int ni = 0; ni < 4; ni++) {
        gwv[ni] = *(const float2*)(g_gw + c0 + ni * 8);
        bbv[ni] = *(const float2*)(b1 + c0 + ni * 8);
    }
    #pragma unroll
    for (int mi = 0; mi < 2; mi++) {
        #pragma unroll
        for (int hf = 0; hf < 2; hf++) {
            const int row = r0 + mi * 16 + hf * 8;
            float s1 = 0.0f, s2 = 0.0f, sp = 0.0f;
            #pragma unroll
            for (int ni = 0; ni < 4; ni++) {
                const float h0 = gelu_exact(acc[mi][ni][hf * 2 + 0] + bbv[ni].x);
                const float h1 = gelu_exact(acc[mi][ni][hf * 2 + 1] + bbv[ni].y);
                s1 += h0 + h1;
                s2 = fmaf(h0, h0, fmaf(h1, h1, s2));
                sp = fmaf(h0, gwv[ni].x, fmaf(h1, gwv[ni].y, sp));
            }
            s1 += __shfl_xor_sync(0xFFFFFFFFu, s1, 1);
            s1 += __shfl_xor_sync(0xFFFFFFFFu, s1, 2);
            s2 += __shfl_xor_sync(0xFFFFFFFFu, s2, 1);
            s2 += __shfl_xor_sync(0xFFFFFFFFu, s2, 2);
            sp += __shfl_xor_sync(0xFFFFFFFFu, sp, 1);
            sp += __shfl_xor_sync(0xFFFFFFFFu, sp, 2);
            if ((l & 3) == 0) {
                atomicAdd(&g_s1[row], s1);
                atomicAdd(&g_s2[row], s2);
                atomicAdd(&g_sp[row], sp);
            }
        }
    }
}

// ---------------------------------------------------------------------------
// final: scores[row] from (S1,S2,SP); replicated 8x along k
// ---------------------------------------------------------------------------
__global__ void __launch_bounds__(256)
final_kernel(float* __restrict__ out) {
    const int r = blockIdx.x * 256 + threadIdx.x;   // < MM
    const float S1 = g_s1[r];
    const float S2 = g_s2[r];
    const float SP = g_sp[r];
    const float mu = S1 * (1.0f / HI);
    const float var = S2 * (1.0f / HI) - mu * mu;
    const float rstd = rsqrtf(var + 1e-12f);
    const float v = rstd * (SP - mu * g_sgw) + g_sbw;

    const int a = r >> 9;
    const int e = r & 511;
    const int m = e >> 3;
    const int j = e & 7;
    const int base = (((a * AA) + m) * EP + j) * EP;
    float4 vv = make_float4(v, v, v, v);
    *(float4*)&out[OFF_SCORES + base]     = vv;
    *(float4*)&out[OFF_SCORES + base + 4] = vv;
}

// ---------------------------------------------------------------------------
// own_gemm: exact fp32  g_hown = GELU(E_own @ W1 + b1)  [512 x 1536], K=768
// Reads the 512 entity rows of E directly (no gather).
// ---------------------------------------------------------------------------
__global__ void __launch_bounds__(256)
own_gemm_kernel(const float* __restrict__ E, const float* __restrict__ W1,
                const float* __restrict__ b1) {
    __shared__ float As[16][64];
    __shared__ float Bs[16][68];
    const int tid = threadIdx.x;
    const int bn = blockIdx.x * 64;
    const int bm = blockIdx.y * 64;
    const int tr = (tid >> 4) * 4;
    const int tc = (tid & 15) * 4;

    float acc[4][4];
    #pragma unroll
    for (int i = 0; i < 4; i++)
        #pragma unroll
        for (int j = 0; j < 4; j++) acc[i][j] = 0.0f;

    const int arow = tid >> 2;           // 0..63 (entity within tile)
    const int acol = (tid & 3) * 4;
    const int brow = tid >> 4;
    const int bcol = (tid & 15) * 4;
    const int e = bm + arow;
    const size_t asrc = ((size_t)(e >> 3) * ETOT + e) * HH;   // E row of entity e

    for (int k0 = 0; k0 < HH; k0 += 16) {
        float4 av = *(const float4*)(E + asrc + k0 + acol);
        As[acol + 0][arow] = av.x;
        As[acol + 1][arow] = av.y;
        As[acol + 2][arow] = av.z;
        As[acol + 3][arow] = av.w;
        float4 bv = *(const float4*)(W1 + (size_t)(k0 + brow) * HI + bn + bcol);
        *(float4*)&Bs[brow][bcol] = bv;
        __syncthreads();

        #pragma unroll
        for (int kk = 0; kk < 16; kk++) {
            float a[4], b[4];
            #pragma unroll
            for (int i = 0; i < 4; i++) a[i] = As[kk][tr + i];
            #pragma unroll
            for (int j = 0; j < 4; j++) b[j] = Bs[kk][tc + j];
            #pragma unroll
            for (int i = 0; i < 4; i++)
                #pragma unroll
                for (int j = 0; j < 4; j++)
                    acc[i][j] = fmaf(a[i], b[j], acc[i][j]);
        }
        __syncthreads();
    }

    #pragma unroll
    for (int i = 0; i < 4; i++) {
        #pragma unroll
        for (int j = 0; j < 4; j++) {
            const int col = bn + tc + j;
            g_hown[(size_t)(bm + tr + i) * HI + col] =
                gelu_exact(acc[i][j] + b1[col]);
        }
    }
}

// ---------------------------------------------------------------------------
// own2: exact LN + 100 logits + softmax-max/argmax per entity (from g_hown).
// Block 511 additionally computes g_gw / g_sgw / g_sbw (prep2 folded in).
// ---------------------------------------------------------------------------
__global__ void __launch_bounds__(512)
own2_kernel(const float* __restrict__ W2, const float* __restrict__ b2,
            const float* __restrict__ lg_, const float* __restrict__ lb_,
            float* __restrict__ out) {
    __shared__ float hs[HI];
    __shared__ float part[4][128];
    __shared__ float lg[DD];
    __shared__ float wr[16];
    __shared__ float wr2[16];
    __shared__ float s_mu, s_rstd;
    __shared__ int   s_sel;
    const int e = blockIdx.x;
    const float* hp = g_hown + (size_t)e * HI;
    const int t = threadIdx.x;

    float s = 0.0f;
    #pragma unroll
    for (int i = t; i < HI; i += 512) { float v = hp[i]; hs[i] = v; s += v; }
    #pragma unroll
    for (int o = 16; o > 0; o >>= 1) s += __shfl_xor_sync(0xFFFFFFFFu, s, o);
    if ((t & 31) == 0) wr[t >> 5] = s;
    __syncthreads();
    if (t == 0) {
        float tot = 0.0f;
        #pragma unroll
        for (int w = 0; w < 16; w++) tot += wr[w];
        s_mu = tot * (1.0f / HI);
    }
    __syncthreads();
    const float mu = s_mu;

    float s2 = 0.0f;
    #pragma unroll
    for (int i = t; i < HI; i += 512) { float d = hs[i] - mu; s2 = fmaf(d, d, s2); }
    #pragma unroll
    for (int o = 16; o > 0; o >>= 1) s2 += __shfl_xor_sync(0xFFFFFFFFu, s2, o);
    if ((t & 31) == 0) wr[t >> 5] = s2;
    __syncthreads();
    if (t == 0) {
        float tot = 0.0f;
        #pragma unroll
        for (int w = 0; w < 16; w++) tot += wr[w];
        s_rstd = rsqrtf(tot * (1.0f / HI) + 1e-12f);
    }
    __syncthreads();
    const float rstd = s_rstd;

    #pragma unroll
    for (int i = t; i < HI; i += 512)
        hs[i] = (hs[i] - mu) * rstd * lg_[i] + lb_[i];
    __syncthreads();

    {
        const int seg = t >> 7;
        const int cls = t & 127;
        float acc = 0.0f;
        if (cls < DD) {
            const int k0 = seg * 384;
            #pragma unroll 8
            for (int k = k0; k < k0 + 384; k++)
                acc = fmaf(hs[k], W2[(size_t)k * DD + cls], acc);
        }
        part[seg][cls] = acc;
    }
    __syncthreads();
    if (t < DD)
        lg[t] = part[0][t] + part[1][t] + part[2][t] + part[3][t] + b2[t];
    __syncthreads();

    if (t == 0) {
        float mx = lg[0]; int ix = 0;
        for (int d = 1; d < DD; d++)
            if (lg[d] > mx) { mx = lg[d]; ix = d; }
        float se = 0.0f;
        for (int d = 0; d < DD; d++) se += expf(lg[d] - mx);
        out[OFF_VGS + e] = 1.0f / se;
        out[OFF_IDX + e] = (float)ix;
        s_sel = ix;
    }

    // prep2 folded into the last block (it owns sel locally)
    if (e == ETOT - 1) {
        __syncthreads();
        const int sel = s_sel;
        float sg = 0.0f, sb = 0.0f;
        #pragma unroll
        for (int i = 0; i < 3; i++) {
            const int k = t + i * 512;
            const float w = W2[(size_t)k * DD + sel];
            const float gw = lg_[k] * w;
            g_gw[k] = gw;
            sg += gw;
            sb += lb_[k] * w;
        }
        #pragma unroll
        for (int o = 16; o > 0; o >>= 1) {
            sg += __shfl_xor_sync(0xFFFFFFFFu, sg, o);
            sb += __shfl_xor_sync(0xFFFFFFFFu, sb, o);
        }
        if ((t & 31) == 0) { wr[t >> 5] = sg; wr2[t >> 5] = sb; }
        __syncthreads();
        if (t == 0) {
            float a = 0.0f, b = 0.0f;
            #pragma unroll
            for (int w = 0; w < 16; w++) { a += wr[w]; b += wr2[w]; }
            g_sgw = a;
            g_sbw = b + b2[sel];
        }
    }
}

// ---------------------------------------------------------------------------
// launch: E, W1, b1, ln_g, ln_b, W2, b2, entity_count
// ---------------------------------------------------------------------------
extern "C" void kernel_launch(void* const* d_in, const int* in_sizes, int n_in,
                              void* d_out, int out_size) {
    const float* E    = (const float*)d_in[0];
    const float* W1   = (const float*)d_in[1];
    const float* b1   = (const float*)d_in[2];
    const float* ln_g = (const float*)d_in[3];
    const float* ln_b = (const float*)d_in[4];
    const float* W2   = (const float*)d_in[5];
    const float* b2   = (const float*)d_in[6];
    float* out = (float*)d_out;

    cudaFuncSetAttribute(gemm_hmma_kernel,
                         cudaFuncAttributeMaxDynamicSharedMemorySize, DYN_SMEM);

    // prep (inputs only); prep_e also zeroes the reduction buffers
    dim3 pb(32, 32);
    dim3 pg(HI / 32, HH / 32);                   // (48, 24)
    prep_w1t_kernel<<<pg, pb>>>(W1);
    prep_e_kernel<<<(MM * HH / 4) / 256, 256>>>(E);

    // exact own-rows path (produces sel -> g_gw for the fused epilogue)
    dim3 og(HI / 64, ETOT / 64);                 // (24, 8)
    own_gemm_kernel<<<og, 256>>>(E, W1, b1);
    own2_kernel<<<ETOT, 512>>>(W2, b2, ln_g, ln_b, out);

    // bulk fp16 path with fused per-row reductions
    dim3 gg(HI / BN, MM / BM);                   // (12, 512)
    gemm_hmma_kernel<<<gg, 256, DYN_SMEM>>>(b1);

    // scores from reductions
    final_kernel<<<MM / 256, 256>>>(out);
}